// round 3
// baseline (speedup 1.0000x reference)
#include <cuda_runtime.h>
#include <cstdint>

#define AA 5
#define THREADS 256
#define ROWS_PB 160
#define GROUPS_PB 32
#define NBLOCKS 4096

// ---------------- precomputed fused weights (hi/lo tf32 splits) ------------
__device__ float g_Wqk_h[AA][96][32];
__device__ float g_Wqk_l[AA][96][32];
__device__ float g_bqk [AA][96];
__device__ float g_Wvo_h[AA][96][32];
__device__ float g_Wvo_l[AA][96][32];
__device__ float g_bvo [AA][96];
__device__ float g_EW_h[272][96];
__device__ float g_EW_l[272][96];

__device__ __forceinline__ float tf32_rna(float v) {
    uint32_t u;
    asm("cvt.rna.tf32.f32 %0, %1;" : "=r"(u) : "f"(v));
    return __uint_as_float(u);
}

__device__ __forceinline__ void split_tf32(float v, uint32_t& h, uint32_t& l) {
    float hf = tf32_rna(v);
    float lf = tf32_rna(v - hf);
    h = __float_as_uint(hf);
    l = __float_as_uint(lf);
}

__device__ __forceinline__ void mma8(float* d,
                                     uint32_t a0, uint32_t a1, uint32_t a2, uint32_t a3,
                                     uint32_t b0, uint32_t b1) {
    asm volatile("mma.sync.aligned.m16n8k8.row.col.f32.tf32.tf32.f32 "
                 "{%0,%1,%2,%3}, {%4,%5,%6,%7}, {%8,%9}, {%0,%1,%2,%3};"
                 : "+f"(d[0]), "+f"(d[1]), "+f"(d[2]), "+f"(d[3])
                 : "r"(a0), "r"(a1), "r"(a2), "r"(a3), "r"(b0), "r"(b1));
}

// ---------------------------- prep kernel ----------------------------------
__global__ void prep_kernel(const float* __restrict__ agg_W,
                            const float* __restrict__ agg_b,
                            const float* __restrict__ ipw,
                            const float* __restrict__ ipb,
                            const float* __restrict__ out_w,
                            const float* __restrict__ extra_w)
{
    int bid = blockIdx.x;
    if (bid < AA) {
        int a = bid;
        for (int o = threadIdx.x; o < 96*32; o += THREADS) {
            int j = o >> 5, c = o & 31;
            float acc = 0.f;
            for (int e = 0; e < 48; e++)
                acc += ipw[j*48+e] * agg_W[(a*48+e)*32 + c];
            uint32_t h, l; split_tf32(acc, h, l);
            g_Wqk_h[a][j][c] = __uint_as_float(h);
            g_Wqk_l[a][j][c] = __uint_as_float(l);
        }
        for (int j = threadIdx.x; j < 96; j += THREADS) {
            float acc = ipb[j];
            for (int e = 0; e < 48; e++)
                acc += ipw[j*48+e] * agg_b[a*48+e];
            g_bqk[a][j] = acc;
        }
    } else if (bid < AA + 2*AA) {
        int a = (bid - AA) >> 1;
        int h = (bid - AA) & 1;
        __shared__ float Wv[24][32];
        __shared__ float bv[24];
        for (int o = threadIdx.x; o < 24*32; o += THREADS) {
            int d = o >> 5, c = o & 31;
            int row = 96 + h*24 + d;
            float acc = 0.f;
            for (int e = 0; e < 48; e++)
                acc += ipw[row*48+e] * agg_W[(a*48+e)*32 + c];
            Wv[d][c] = acc;
        }
        for (int d = threadIdx.x; d < 24; d += THREADS) {
            int row = 96 + h*24 + d;
            float acc = ipb[row];
            for (int e = 0; e < 48; e++)
                acc += ipw[row*48+e] * agg_b[a*48+e];
            bv[d] = acc;
        }
        __syncthreads();
        for (int o = threadIdx.x; o < 48*32; o += THREADS) {
            int e = o >> 5, c = o & 31;
            float acc = 0.f;
            for (int d = 0; d < 24; d++)
                acc += Wv[d][c] * out_w[e*48 + h*24 + d];
            uint32_t hh, ll; split_tf32(acc, hh, ll);
            g_Wvo_h[a][h*48 + e][c] = __uint_as_float(hh);
            g_Wvo_l[a][h*48 + e][c] = __uint_as_float(ll);
        }
        for (int e = threadIdx.x; e < 48; e += THREADS) {
            float acc = 0.f;
            for (int d = 0; d < 24; d++)
                acc += bv[d] * out_w[e*48 + h*24 + d];
            g_bvo[a][h*48 + e] = acc;
        }
    } else {
        // extra_w hi/lo split: 2 blocks cover 272*96 elems
        int part = bid - 3*AA;            // 0 or 1
        int beg = part * (272*96/2);
        int end = beg + (272*96/2);
        for (int o = beg + threadIdx.x; o < end; o += THREADS) {
            float v = extra_w[o];
            uint32_t h, l; split_tf32(v, h, l);
            g_EW_h[0][o] = __uint_as_float(h);   // flat index
            g_EW_l[0][o] = __uint_as_float(l);
        }
    }
}

// ---------------------------- main kernel ----------------------------------
// Shared layout (floats):
//   xs : 160 rows x pitch 36  (x agg slices; stage5 reuses as xe 32x pitch100)
//   ws : 13824 (two weight sets of [hi 96x36][lo 96x36]; stage5: [hi 64x100][lo 64x100])
//   qk : 160 x pitch 98 (GEMM results, qk then vo)
//   pb : 32 x 50 (softmax probs)
#define XS_PITCH 36
#define QK_PITCH 98
#define SM_XS 0
#define SM_WS (160*XS_PITCH)                 // 5760
#define WSET  (96*XS_PITCH*2)                // 6912 floats per set (hi+lo)
#define WLO   (96*XS_PITCH)                  // lo offset within set
#define SM_QK (SM_WS + 2*WSET)               // 5760+13824 = 19584
#define SM_PB (SM_QK + 160*QK_PITCH)         // +15680 = 35264
#define SM_FLOATS (SM_PB + GROUPS_PB*50)     // 36864 -> 147456 B

__device__ __forceinline__ long row_xoff(int r)
{
    int a  = (r >> 12) % 5;
    int tx = (r / 20480) * 4096 + (r & 4095);
    return (long)tx * 256 + a * 32;
}

__global__ void __launch_bounds__(THREADS, 1)
main_kernel(const float* __restrict__ x,
            const float* __restrict__ extra_b,
            const float* __restrict__ out_b,
            float* __restrict__ out)
{
    extern __shared__ float sm[];
    float* xs = sm + SM_XS;
    float* ws = sm + SM_WS;
    float* qk = sm + SM_QK;
    float* pb = sm + SM_PB;

    const int tid  = threadIdx.x;
    const int lane = tid & 31;
    const int warp = tid >> 5;
    const int g4   = lane >> 2;      // 0..7
    const int t4   = lane & 3;       // 0..3
    const int z    = tid & 15;
    const int t0   = tid >> 4;

    const int r0    = blockIdx.x * ROWS_PB;
    const int m0tok = blockIdx.x * GROUPS_PB;

    const int  blk4k = r0 >> 12;
    const int  a_lo  = blk4k % 5;
    const int  Bnd   = (blk4k + 1) << 12;
    const bool has_b = (r0 + ROWS_PB) > Bnd;
    const int  a_hi  = has_b ? ((a_lo + 1) % 5) : a_lo;

    // ---- phase 0: stage x rows + qk weights (both sets if boundary) -------
    for (int i = tid; i < 1280; i += THREADS) {        // 160 rows * 8 float4
        int row = i >> 3, q = i & 7;
        const float4 v = *(const float4*)(x + row_xoff(r0 + row) + q*4);
        *(float4*)&xs[row*XS_PITCH + q*4] = v;
    }
    for (int i = tid; i < 96*32; i += THREADS) {
        int j = i >> 5, c = i & 31;
        ws[j*XS_PITCH + c]       = g_Wqk_h[a_lo][j][c];
        ws[WLO + j*XS_PITCH + c] = g_Wqk_l[a_lo][j][c];
        if (has_b) {
            ws[WSET + j*XS_PITCH + c]       = g_Wqk_h[a_hi][j][c];
            ws[WSET + WLO + j*XS_PITCH + c] = g_Wqk_l[a_hi][j][c];
        }
    }
    __syncthreads();

    // ---- phase 1: GEMM qk : D[160x96] -------------------------------------
    #pragma unroll 1
    for (int t = 0; t < 5; t++) {
        int task = warp*5 + t;                  // 0..39
        int mt = task >> 2, ng = task & 3;
        bool hiset = has_b && (r0 + mt*16) >= Bnd;
        const float* wsb = ws + (hiset ? WSET : 0);
        int a_t = hiset ? a_hi : a_lo;
        int arow = mt*16 + g4;

        float acc[3][4];
        #pragma unroll
        for (int nj = 0; nj < 3; nj++)
            #pragma unroll
            for (int q = 0; q < 4; q++) acc[nj][q] = 0.f;

        #pragma unroll
        for (int ks = 0; ks < 4; ks++) {
            const float* ap = xs + arow*XS_PITCH + ks*8 + t4;
            float a0 = ap[0], a2 = ap[4];
            float a1 = ap[8*XS_PITCH], a3 = ap[8*XS_PITCH + 4];
            uint32_t ah0,al0,ah1,al1,ah2,al2,ah3,al3;
            split_tf32(a0, ah0, al0); split_tf32(a1, ah1, al1);
            split_tf32(a2, ah2, al2); split_tf32(a3, ah3, al3);
            #pragma unroll
            for (int nj = 0; nj < 3; nj++) {
                const float* bp = wsb + ((ng*3+nj)*8 + g4)*XS_PITCH + ks*8 + t4;
                uint32_t bh0 = __float_as_uint(bp[0]);
                uint32_t bh1 = __float_as_uint(bp[4]);
                uint32_t bl0 = __float_as_uint(bp[WLO]);
                uint32_t bl1 = __float_as_uint(bp[WLO + 4]);
                mma8(acc[nj], ah0,ah1,ah2,ah3, bh0,bh1);
                mma8(acc[nj], ah0,ah1,ah2,ah3, bl0,bl1);
                mma8(acc[nj], al0,al1,al2,al3, bh0,bh1);
            }
        }
        #pragma unroll
        for (int nj = 0; nj < 3; nj++) {
            int j0 = (ng*3+nj)*8 + 2*t4;
            float b0 = g_bqk[a_t][j0], b1 = g_bqk[a_t][j0+1];
            float2 v0 = make_float2(acc[nj][0]+b0, acc[nj][1]+b1);
            float2 v1 = make_float2(acc[nj][2]+b0, acc[nj][3]+b1);
            *(float2*)&qk[(mt*16+g4  )*QK_PITCH + j0] = v0;
            *(float2*)&qk[(mt*16+g4+8)*QK_PITCH + j0] = v1;
        }
    }
    __syncthreads();

    // ---- phase 2: softmax + restage ws with vo weights ---------------------
    if (z < 10) {
        int h = z / 5, i = z % 5;
        #pragma unroll
        for (int pick = 0; pick < 2; pick++) {
            int g = t0 + pick*16;
            const float* gb = qk + g*5*QK_PITCH;
            float s[5]; float mx = -1e30f;
            #pragma unroll
            for (int j = 0; j < 5; j++) {
                float a = 0.f;
                const float* qp = gb + i*QK_PITCH + h*24;
                const float* kp = gb + j*QK_PITCH + 48 + h*24;
                #pragma unroll
                for (int d = 0; d < 24; d++) a = fmaf(qp[d], kp[d], a);
                s[j] = a * 0.20412414523193154f;
                mx = fmaxf(mx, s[j]);
            }
            float sum = 0.f;
            #pragma unroll
            for (int j = 0; j < 5; j++) { s[j] = __expf(s[j]-mx); sum += s[j]; }
            float inv = 1.f / sum;
            #pragma unroll
            for (int j = 0; j < 5; j++) pb[g*50 + z*5 + j] = s[j]*inv;
        }
    }
    for (int i = tid; i < 96*32; i += THREADS) {
        int j = i >> 5, c = i & 31;
        ws[j*XS_PITCH + c]       = g_Wvo_h[a_lo][j][c];
        ws[WLO + j*XS_PITCH + c] = g_Wvo_l[a_lo][j][c];
        if (has_b) {
            ws[WSET + j*XS_PITCH + c]       = g_Wvo_h[a_hi][j][c];
            ws[WSET + WLO + j*XS_PITCH + c] = g_Wvo_l[a_hi][j][c];
        }
    }
    __syncthreads();

    // ---- phase 3: GEMM vo (overwrites qk buffer) ---------------------------
    #pragma unroll 1
    for (int t = 0; t < 5; t++) {
        int task = warp*5 + t;
        int mt = task >> 2, ng = task & 3;
        bool hiset = has_b && (r0 + mt*16) >= Bnd;
        const float* wsb = ws + (hiset ? WSET : 0);
        int a_t = hiset ? a_hi : a_lo;
        int arow = mt*16 + g4;

        float acc[3][4];
        #pragma unroll
        for (int nj = 0; nj < 3; nj++)
            #pragma unroll
            for (int q = 0; q < 4; q++) acc[nj][q] = 0.f;

        #pragma unroll
        for (int ks = 0; ks < 4; ks++) {
            const float* ap = xs + arow*XS_PITCH + ks*8 + t4;
            float a0 = ap[0], a2 = ap[4];
            float a1 = ap[8*XS_PITCH], a3 = ap[8*XS_PITCH + 4];
            uint32_t ah0,al0,ah1,al1,ah2,al2,ah3,al3;
            split_tf32(a0, ah0, al0); split_tf32(a1, ah1, al1);
            split_tf32(a2, ah2, al2); split_tf32(a3, ah3, al3);
            #pragma unroll
            for (int nj = 0; nj < 3; nj++) {
                const float* bp = wsb + ((ng*3+nj)*8 + g4)*XS_PITCH + ks*8 + t4;
                uint32_t bh0 = __float_as_uint(bp[0]);
                uint32_t bh1 = __float_as_uint(bp[4]);
                uint32_t bl0 = __float_as_uint(bp[WLO]);
                uint32_t bl1 = __float_as_uint(bp[WLO + 4]);
                mma8(acc[nj], ah0,ah1,ah2,ah3, bh0,bh1);
                mma8(acc[nj], ah0,ah1,ah2,ah3, bl0,bl1);
                mma8(acc[nj], al0,al1,al2,al3, bh0,bh1);
            }
        }
        #pragma unroll
        for (int nj = 0; nj < 3; nj++) {
            int j0 = (ng*3+nj)*8 + 2*t4;
            float b0 = g_bvo[a_t][j0], b1 = g_bvo[a_t][j0+1];
            float2 v0 = make_float2(acc[nj][0]+b0, acc[nj][1]+b1);
            float2 v1 = make_float2(acc[nj][2]+b0, acc[nj][3]+b1);
            *(float2*)&qk[(mt*16+g4  )*QK_PITCH + j0] = v0;
            *(float2*)&qk[(mt*16+g4+8)*QK_PITCH + j0] = v1;
        }
    }
    __syncthreads();

    // ---- phase 4: combine -> out cols [0,240); stage xe into xs region ----
    #pragma unroll
    for (int m = 0; m < 15; m++) {
        int col = z + 16*m;
        int i = col / 48, e = col % 48;
        float ob = out_b[e];
        float acc0 = ob, acc1 = ob;
        int gA = t0, gB = t0 + 16;
        #pragma unroll
        for (int h = 0; h < 2; h++) {
            #pragma unroll
            for (int j = 0; j < 5; j++) {
                float p0 = pb[gA*50 + (h*5+i)*5 + j];
                float p1 = pb[gB*50 + (h*5+i)*5 + j];
                float v0 = qk[(gA*5+j)*QK_PITCH + h*48 + e];
                float v1 = qk[(gB*5+j)*QK_PITCH + h*48 + e];
                acc0 = fmaf(p0, v0, acc0);
                acc1 = fmaf(p1, v1, acc1);
            }
        }
        out[(long)(m0tok+gA)*512 + col] = acc0;
        out[(long)(m0tok+gB)*512 + col] = acc1;
    }
    // xe: 32 tokens x 96 extra feats, pitch 100 (xs region, 3200 <= 5760)
    for (int i = tid; i < 768; i += THREADS) {          // 32 * 24 float4
        int tok = i / 24, q = i % 24;
        const float4 v = *(const float4*)(x + (long)(m0tok + tok)*256 + 160 + q*4);
        *(float4*)&xs[tok*100 + q*4] = v;
    }
    __syncthreads();

    // ---- phase 5: extra GEMM [32x96] @ [96 x 272] in chunks of 64 cols ----
    #pragma unroll 1
    for (int chunk = 0; chunk < 5; chunk++) {
        int u0 = chunk * 64;
        int R  = (272 - u0) < 64 ? (272 - u0) : 64;     // 64,64,64,64,16
        if (chunk) __syncthreads();                      // prev mma done before restage
        for (int i = tid; i < R*96; i += THREADS) {
            int r = i / 96, c = i % 96;
            ws[r*100 + c]        = g_EW_h[u0 + r][c];
            ws[6400 + r*100 + c] = g_EW_l[u0 + r][c];
        }
        __syncthreads();

        int tasks = 2 * (R >> 3);                        // 16 or 4
        for (int tt = warp; tt < tasks; tt += 8) {
            int mt = tt & 1, nl = tt >> 1;
            float acc[4] = {0.f, 0.f, 0.f, 0.f};
            #pragma unroll
            for (int ks = 0; ks < 12; ks++) {
                const float* ap = xs + (mt*16 + g4)*100 + ks*8 + t4;
                float a0 = ap[0], a2 = ap[4];
                float a1 = ap[800], a3 = ap[804];
                uint32_t ah0,al0,ah1,al1,ah2,al2,ah3,al3;
                split_tf32(a0, ah0, al0); split_tf32(a1, ah1, al1);
                split_tf32(a2, ah2, al2); split_tf32(a3, ah3, al3);
                const float* bp = ws + (nl*8 + g4)*100 + ks*8 + t4;
                uint32_t bh0 = __float_as_uint(bp[0]);
                uint32_t bh1 = __float_as_uint(bp[4]);
                uint32_t bl0 = __float_as_uint(bp[6400]);
                uint32_t bl1 = __float_as_uint(bp[6404]);
                mma8(acc, ah0,ah1,ah2,ah3, bh0,bh1);
                mma8(acc, ah0,ah1,ah2,ah3, bl0,bl1);
                mma8(acc, al0,al1,al2,al3, bh0,bh1);
            }
            int u = u0 + nl*8 + 2*t4;
            float bb0 = extra_b[u], bb1 = extra_b[u+1];
            long tok = m0tok + mt*16 + g4;
            *(float2*)&out[tok*512 + 240 + u] =
                make_float2(acc[0]+bb0, acc[1]+bb1);
            *(float2*)&out[(tok+8)*512 + 240 + u] =
                make_float2(acc[2]+bb0, acc[3]+bb1);
        }
    }
}

extern "C" void kernel_launch(void* const* d_in, const int* in_sizes, int n_in,
                              void* d_out, int out_size)
{
    const float *x=0, *agg_W=0, *agg_b=0, *ipw=0, *ipb=0, *out_w=0, *out_b=0, *extra_w=0, *extra_b=0;
    for (int i = 0; i < n_in; i++) {
        switch (in_sizes[i]) {
            case 32*4096*256: x       = (const float*)d_in[i]; break;
            case 5*48*32:     agg_W   = (const float*)d_in[i]; break;
            case 5*48:        agg_b   = (const float*)d_in[i]; break;
            case 144*48:      ipw     = (const float*)d_in[i]; break;
            case 144:         ipb     = (const float*)d_in[i]; break;
            case 48*48:       out_w   = (const float*)d_in[i]; break;
            case 48:          out_b   = (const float*)d_in[i]; break;
            case 272*96:      extra_w = (const float*)d_in[i]; break;
            case 272:         extra_b = (const float*)d_in[i]; break;
            default: break;
        }
    }
    float* out = (float*)d_out;

    prep_kernel<<<17, THREADS>>>(agg_W, agg_b, ipw, ipb, out_w, extra_w);

    const int smem_bytes = SM_FLOATS * (int)sizeof(float);   // 147456
    cudaFuncSetAttribute(main_kernel, cudaFuncAttributeMaxDynamicSharedMemorySize, smem_bytes);
    main_kernel<<<NBLOCKS, THREADS, smem_bytes>>>(x, extra_b, out_b, out);
}

// round 4
// speedup vs baseline: 1.2616x; 1.2616x over previous
#include <cuda_runtime.h>
#include <cstdint>

#define AA 5
#define THREADS 512
#define ROWS_PB 160
#define GROUPS_PB 32
#define NBLOCKS 4096

// ---------------- precomputed fused weights (hi/lo tf32 splits) ------------
__device__ float g_Wqk_h[AA][96][32];
__device__ float g_Wqk_l[AA][96][32];
__device__ float g_bqk [AA][96];
__device__ float g_Wvo_h[AA][96][32];
__device__ float g_Wvo_l[AA][96][32];
__device__ float g_bvo [AA][96];
__device__ float g_EW_h[272][96];
__device__ float g_EW_l[272][96];

__device__ __forceinline__ float tf32_rna(float v) {
    uint32_t u;
    asm("cvt.rna.tf32.f32 %0, %1;" : "=r"(u) : "f"(v));
    return __uint_as_float(u);
}

__device__ __forceinline__ void split_tf32(float v, float& h, float& l) {
    h = tf32_rna(v);
    l = tf32_rna(v - h);
}

__device__ __forceinline__ void mma8(float* d,
                                     uint32_t a0, uint32_t a1, uint32_t a2, uint32_t a3,
                                     uint32_t b0, uint32_t b1) {
    asm volatile("mma.sync.aligned.m16n8k8.row.col.f32.tf32.tf32.f32 "
                 "{%0,%1,%2,%3}, {%4,%5,%6,%7}, {%8,%9}, {%0,%1,%2,%3};"
                 : "+f"(d[0]), "+f"(d[1]), "+f"(d[2]), "+f"(d[3])
                 : "r"(a0), "r"(a1), "r"(a2), "r"(a3), "r"(b0), "r"(b1));
}

// ---------------------------- prep kernel ----------------------------------
#define PREP_T 256
__global__ void prep_kernel(const float* __restrict__ agg_W,
                            const float* __restrict__ agg_b,
                            const float* __restrict__ ipw,
                            const float* __restrict__ ipb,
                            const float* __restrict__ out_w,
                            const float* __restrict__ extra_w)
{
    int bid = blockIdx.x;
    if (bid < AA) {
        int a = bid;
        for (int o = threadIdx.x; o < 96*32; o += PREP_T) {
            int j = o >> 5, c = o & 31;
            float acc = 0.f;
            for (int e = 0; e < 48; e++)
                acc += ipw[j*48+e] * agg_W[(a*48+e)*32 + c];
            float h, l; split_tf32(acc, h, l);
            g_Wqk_h[a][j][c] = h;
            g_Wqk_l[a][j][c] = l;
        }
        for (int j = threadIdx.x; j < 96; j += PREP_T) {
            float acc = ipb[j];
            for (int e = 0; e < 48; e++)
                acc += ipw[j*48+e] * agg_b[a*48+e];
            g_bqk[a][j] = acc;
        }
    } else if (bid < AA + 2*AA) {
        int a = (bid - AA) >> 1;
        int h = (bid - AA) & 1;
        __shared__ float Wv[24][32];
        __shared__ float bv[24];
        for (int o = threadIdx.x; o < 24*32; o += PREP_T) {
            int d = o >> 5, c = o & 31;
            int row = 96 + h*24 + d;
            float acc = 0.f;
            for (int e = 0; e < 48; e++)
                acc += ipw[row*48+e] * agg_W[(a*48+e)*32 + c];
            Wv[d][c] = acc;
        }
        for (int d = threadIdx.x; d < 24; d += PREP_T) {
            int row = 96 + h*24 + d;
            float acc = ipb[row];
            for (int e = 0; e < 48; e++)
                acc += ipw[row*48+e] * agg_b[a*48+e];
            bv[d] = acc;
        }
        __syncthreads();
        for (int o = threadIdx.x; o < 48*32; o += PREP_T) {
            int e = o >> 5, c = o & 31;
            float acc = 0.f;
            for (int d = 0; d < 24; d++)
                acc += Wv[d][c] * out_w[e*48 + h*24 + d];
            float hh, ll; split_tf32(acc, hh, ll);
            g_Wvo_h[a][h*48 + e][c] = hh;
            g_Wvo_l[a][h*48 + e][c] = ll;
        }
        for (int e = threadIdx.x; e < 48; e += PREP_T) {
            float acc = 0.f;
            for (int d = 0; d < 24; d++)
                acc += bv[d] * out_w[e*48 + h*24 + d];
            g_bvo[a][h*48 + e] = acc;
        }
    } else {
        int part = bid - 3*AA;
        int beg = part * (272*96/2);
        int end = beg + (272*96/2);
        for (int o = beg + threadIdx.x; o < end; o += PREP_T) {
            float v = extra_w[o];
            float h, l; split_tf32(v, h, l);
            g_EW_h[0][o] = h;
            g_EW_l[0][o] = l;
        }
    }
}

// ---------------------------- main kernel ----------------------------------
// Shared layout (floats):
//   xs_h,xs_l : 160 x 36 each  (pre-split x agg slices; phase5 reuses as xe 32x100)
//   ws        : two sets of [hi 96x36][lo 96x36]  (phase5: [hi 64x100][lo 64x100])
//   qk        : 160 x 98 (GEMM results: qk, then vo)
//   pb        : 32 x 50  (softmax probs)
#define XS_PITCH 36
#define QK_PITCH 98
#define SM_XSH 0
#define SM_XSL (160*XS_PITCH)                // 5760
#define SM_WS  (2*160*XS_PITCH)              // 11520
#define WLO    (96*XS_PITCH)                 // 3456
#define WSET   (2*96*XS_PITCH)               // 6912
#define SM_QK  (SM_WS + 2*WSET)              // 25344
#define SM_PB  (SM_QK + 160*QK_PITCH)        // 41024
#define SM_FLOATS (SM_PB + GROUPS_PB*50)     // 42624 -> 170496 B

__device__ __forceinline__ long row_xoff(int r)
{
    int a  = (r >> 12) % 5;
    int tx = (r / 20480) * 4096 + (r & 4095);
    return (long)tx * 256 + a * 32;
}

__global__ void __launch_bounds__(THREADS, 1)
main_kernel(const float* __restrict__ x,
            const float* __restrict__ extra_b,
            const float* __restrict__ out_b,
            float* __restrict__ out)
{
    extern __shared__ float sm[];
    float* xsh = sm + SM_XSH;
    float* xsl = sm + SM_XSL;
    float* ws  = sm + SM_WS;
    float* qk  = sm + SM_QK;
    float* pb  = sm + SM_PB;

    const int tid  = threadIdx.x;
    const int lane = tid & 31;
    const int warp = tid >> 5;       // 0..15
    const int g4   = lane >> 2;
    const int t4   = lane & 3;
    const int z    = tid & 15;
    const int t0   = tid >> 4;       // 0..31

    const int r0    = blockIdx.x * ROWS_PB;
    const int m0tok = blockIdx.x * GROUPS_PB;

    const int  blk4k = r0 >> 12;
    const int  a_lo  = blk4k % 5;
    const int  Bnd   = (blk4k + 1) << 12;
    const bool has_b = (r0 + ROWS_PB) > Bnd;
    const int  a_hi  = has_b ? ((a_lo + 1) % 5) : a_lo;

    // ---- phase 0: stage x rows (pre-split hi/lo) + qk weights --------------
    for (int i = tid; i < 1280; i += THREADS) {        // 160 rows * 8 float4
        int row = i >> 3, q = i & 7;
        const float4 v = *(const float4*)(x + row_xoff(r0 + row) + q*4);
        float h0,l0,h1,l1,h2,l2,h3,l3;
        split_tf32(v.x, h0, l0); split_tf32(v.y, h1, l1);
        split_tf32(v.z, h2, l2); split_tf32(v.w, h3, l3);
        float* ph = xsh + row*XS_PITCH + q*4;
        float* pl = xsl + row*XS_PITCH + q*4;
        ph[0]=h0; ph[1]=h1; ph[2]=h2; ph[3]=h3;
        pl[0]=l0; pl[1]=l1; pl[2]=l2; pl[3]=l3;
    }
    for (int i = tid; i < 96*32; i += THREADS) {
        int j = i >> 5, c = i & 31;
        ws[j*XS_PITCH + c]       = g_Wqk_h[a_lo][j][c];
        ws[WLO + j*XS_PITCH + c] = g_Wqk_l[a_lo][j][c];
        if (has_b) {
            ws[WSET + j*XS_PITCH + c]       = g_Wqk_h[a_hi][j][c];
            ws[WSET + WLO + j*XS_PITCH + c] = g_Wqk_l[a_hi][j][c];
        }
    }
    __syncthreads();

    // ---- phase 1: GEMM qk : D[160x96] --------------------------------------
    #pragma unroll 1
    for (int task = warp; task < 40; task += 16) {
        int mt = task >> 2, ng = task & 3;
        bool hiset = has_b && (r0 + mt*16) >= Bnd;
        const float* wsb = ws + (hiset ? WSET : 0);
        int a_t = hiset ? a_hi : a_lo;
        int arow = mt*16 + g4;

        float acc[3][4];
        #pragma unroll
        for (int nj = 0; nj < 3; nj++)
            #pragma unroll
            for (int q = 0; q < 4; q++) acc[nj][q] = 0.f;

        #pragma unroll
        for (int ks = 0; ks < 4; ks++) {
            const float* aph = xsh + arow*XS_PITCH + ks*8 + t4;
            const float* apl = xsl + arow*XS_PITCH + ks*8 + t4;
            uint32_t ah0 = __float_as_uint(aph[0]);
            uint32_t ah2 = __float_as_uint(aph[4]);
            uint32_t ah1 = __float_as_uint(aph[8*XS_PITCH]);
            uint32_t ah3 = __float_as_uint(aph[8*XS_PITCH + 4]);
            uint32_t al0 = __float_as_uint(apl[0]);
            uint32_t al2 = __float_as_uint(apl[4]);
            uint32_t al1 = __float_as_uint(apl[8*XS_PITCH]);
            uint32_t al3 = __float_as_uint(apl[8*XS_PITCH + 4]);
            #pragma unroll
            for (int nj = 0; nj < 3; nj++) {
                const float* bp = wsb + ((ng*3+nj)*8 + g4)*XS_PITCH + ks*8 + t4;
                uint32_t bh0 = __float_as_uint(bp[0]);
                uint32_t bh1 = __float_as_uint(bp[4]);
                uint32_t bl0 = __float_as_uint(bp[WLO]);
                uint32_t bl1 = __float_as_uint(bp[WLO + 4]);
                mma8(acc[nj], ah0,ah1,ah2,ah3, bh0,bh1);
                mma8(acc[nj], ah0,ah1,ah2,ah3, bl0,bl1);
                mma8(acc[nj], al0,al1,al2,al3, bh0,bh1);
            }
        }
        #pragma unroll
        for (int nj = 0; nj < 3; nj++) {
            int j0 = (ng*3+nj)*8 + 2*t4;
            float b0 = g_bqk[a_t][j0], b1 = g_bqk[a_t][j0+1];
            *(float2*)&qk[(mt*16+g4  )*QK_PITCH + j0] =
                make_float2(acc[nj][0]+b0, acc[nj][1]+b1);
            *(float2*)&qk[(mt*16+g4+8)*QK_PITCH + j0] =
                make_float2(acc[nj][2]+b0, acc[nj][3]+b1);
        }
    }
    __syncthreads();

    // ---- phase 2: softmax + restage ws with vo weights ---------------------
    if (z < 10) {
        int h = z / 5, i = z % 5;
        int g = t0;
        const float* gb = qk + g*5*QK_PITCH;
        float s[5]; float mx = -1e30f;
        #pragma unroll
        for (int j = 0; j < 5; j++) {
            float a = 0.f;
            const float* qp = gb + i*QK_PITCH + h*24;
            const float* kp = gb + j*QK_PITCH + 48 + h*24;
            #pragma unroll
            for (int d = 0; d < 24; d++) a = fmaf(qp[d], kp[d], a);
            s[j] = a * 0.20412414523193154f;
            mx = fmaxf(mx, s[j]);
        }
        float sum = 0.f;
        #pragma unroll
        for (int j = 0; j < 5; j++) { s[j] = __expf(s[j]-mx); sum += s[j]; }
        float inv = 1.f / sum;
        #pragma unroll
        for (int j = 0; j < 5; j++) pb[g*50 + z*5 + j] = s[j]*inv;
    }
    for (int i = tid; i < 96*32; i += THREADS) {
        int j = i >> 5, c = i & 31;
        ws[j*XS_PITCH + c]       = g_Wvo_h[a_lo][j][c];
        ws[WLO + j*XS_PITCH + c] = g_Wvo_l[a_lo][j][c];
        if (has_b) {
            ws[WSET + j*XS_PITCH + c]       = g_Wvo_h[a_hi][j][c];
            ws[WSET + WLO + j*XS_PITCH + c] = g_Wvo_l[a_hi][j][c];
        }
    }
    __syncthreads();

    // ---- phase 3: GEMM vo (overwrites qk buffer) ---------------------------
    #pragma unroll 1
    for (int task = warp; task < 40; task += 16) {
        int mt = task >> 2, ng = task & 3;
        bool hiset = has_b && (r0 + mt*16) >= Bnd;
        const float* wsb = ws + (hiset ? WSET : 0);
        int a_t = hiset ? a_hi : a_lo;
        int arow = mt*16 + g4;

        float acc[3][4];
        #pragma unroll
        for (int nj = 0; nj < 3; nj++)
            #pragma unroll
            for (int q = 0; q < 4; q++) acc[nj][q] = 0.f;

        #pragma unroll
        for (int ks = 0; ks < 4; ks++) {
            const float* aph = xsh + arow*XS_PITCH + ks*8 + t4;
            const float* apl = xsl + arow*XS_PITCH + ks*8 + t4;
            uint32_t ah0 = __float_as_uint(aph[0]);
            uint32_t ah2 = __float_as_uint(aph[4]);
            uint32_t ah1 = __float_as_uint(aph[8*XS_PITCH]);
            uint32_t ah3 = __float_as_uint(aph[8*XS_PITCH + 4]);
            uint32_t al0 = __float_as_uint(apl[0]);
            uint32_t al2 = __float_as_uint(apl[4]);
            uint32_t al1 = __float_as_uint(apl[8*XS_PITCH]);
            uint32_t al3 = __float_as_uint(apl[8*XS_PITCH + 4]);
            #pragma unroll
            for (int nj = 0; nj < 3; nj++) {
                const float* bp = wsb + ((ng*3+nj)*8 + g4)*XS_PITCH + ks*8 + t4;
                uint32_t bh0 = __float_as_uint(bp[0]);
                uint32_t bh1 = __float_as_uint(bp[4]);
                uint32_t bl0 = __float_as_uint(bp[WLO]);
                uint32_t bl1 = __float_as_uint(bp[WLO + 4]);
                mma8(acc[nj], ah0,ah1,ah2,ah3, bh0,bh1);
                mma8(acc[nj], ah0,ah1,ah2,ah3, bl0,bl1);
                mma8(acc[nj], al0,al1,al2,al3, bh0,bh1);
            }
        }
        #pragma unroll
        for (int nj = 0; nj < 3; nj++) {
            int j0 = (ng*3+nj)*8 + 2*t4;
            float b0 = g_bvo[a_t][j0], b1 = g_bvo[a_t][j0+1];
            *(float2*)&qk[(mt*16+g4  )*QK_PITCH + j0] =
                make_float2(acc[nj][0]+b0, acc[nj][1]+b1);
            *(float2*)&qk[(mt*16+g4+8)*QK_PITCH + j0] =
                make_float2(acc[nj][2]+b0, acc[nj][3]+b1);
        }
    }
    __syncthreads();

    // ---- phase 4: combine -> out cols [0,240); stage xe (split) -----------
    {
        int g = t0;
        #pragma unroll
        for (int m = 0; m < 15; m++) {
            int col = z + 16*m;
            int i = col / 48, e = col % 48;
            float acc = out_b[e];
            #pragma unroll
            for (int h = 0; h < 2; h++) {
                #pragma unroll
                for (int j = 0; j < 5; j++) {
                    float p = pb[g*50 + (h*5+i)*5 + j];
                    float v = qk[(g*5+j)*QK_PITCH + h*48 + e];
                    acc = fmaf(p, v, acc);
                }
            }
            out[(long)(m0tok+g)*512 + col] = acc;
        }
    }
    // xe: 32 tokens x 96 feats, pitch 100, hi in xsh region, lo in xsl region
    for (int i = tid; i < 768; i += THREADS) {          // 32 * 24 float4
        int tok = i / 24, q = i % 24;
        const float4 v = *(const float4*)(x + (long)(m0tok + tok)*256 + 160 + q*4);
        float h0,l0,h1,l1,h2,l2,h3,l3;
        split_tf32(v.x, h0, l0); split_tf32(v.y, h1, l1);
        split_tf32(v.z, h2, l2); split_tf32(v.w, h3, l3);
        float* ph = xsh + tok*100 + q*4;
        float* pl = xsl + tok*100 + q*4;
        ph[0]=h0; ph[1]=h1; ph[2]=h2; ph[3]=h3;
        pl[0]=l0; pl[1]=l1; pl[2]=l2; pl[3]=l3;
    }
    __syncthreads();

    // ---- phase 5: extra GEMM [32x96] @ [96 x 272] in chunks of 64 cols -----
    #pragma unroll 1
    for (int chunk = 0; chunk < 5; chunk++) {
        int u0 = chunk * 64;
        int R  = (272 - u0) < 64 ? (272 - u0) : 64;     // 64,64,64,64,16
        if (chunk) __syncthreads();
        for (int i = tid; i < R*96; i += THREADS) {
            int r = i / 96, c = i % 96;
            ws[r*100 + c]        = g_EW_h[u0 + r][c];
            ws[6400 + r*100 + c] = g_EW_l[u0 + r][c];
        }
        __syncthreads();

        int tasks = 2 * (R >> 3);                        // 16 or 4
        if (warp < tasks) {
            int mt = warp & 1, nl = warp >> 1;
            float acc[4] = {0.f, 0.f, 0.f, 0.f};
            #pragma unroll
            for (int ks = 0; ks < 12; ks++) {
                const float* aph = xsh + (mt*16 + g4)*100 + ks*8 + t4;
                const float* apl = xsl + (mt*16 + g4)*100 + ks*8 + t4;
                uint32_t ah0 = __float_as_uint(aph[0]);
                uint32_t ah2 = __float_as_uint(aph[4]);
                uint32_t ah1 = __float_as_uint(aph[800]);
                uint32_t ah3 = __float_as_uint(aph[804]);
                uint32_t al0 = __float_as_uint(apl[0]);
                uint32_t al2 = __float_as_uint(apl[4]);
                uint32_t al1 = __float_as_uint(apl[800]);
                uint32_t al3 = __float_as_uint(apl[804]);
                const float* bp = ws + (nl*8 + g4)*100 + ks*8 + t4;
                uint32_t bh0 = __float_as_uint(bp[0]);
                uint32_t bh1 = __float_as_uint(bp[4]);
                uint32_t bl0 = __float_as_uint(bp[6400]);
                uint32_t bl1 = __float_as_uint(bp[6404]);
                mma8(acc, ah0,ah1,ah2,ah3, bh0,bh1);
                mma8(acc, ah0,ah1,ah2,ah3, bl0,bl1);
                mma8(acc, al0,al1,al2,al3, bh0,bh1);
            }
            int u = u0 + nl*8 + 2*t4;
            float bb0 = extra_b[u], bb1 = extra_b[u+1];
            long tok = m0tok + mt*16 + g4;
            *(float2*)&out[tok*512 + 240 + u] =
                make_float2(acc[0]+bb0, acc[1]+bb1);
            *(float2*)&out[(tok+8)*512 + 240 + u] =
                make_float2(acc[2]+bb0, acc[3]+bb1);
        }
    }
}

extern "C" void kernel_launch(void* const* d_in, const int* in_sizes, int n_in,
                              void* d_out, int out_size)
{
    const float *x=0, *agg_W=0, *agg_b=0, *ipw=0, *ipb=0, *out_w=0, *out_b=0, *extra_w=0, *extra_b=0;
    for (int i = 0; i < n_in; i++) {
        switch (in_sizes[i]) {
            case 32*4096*256: x       = (const float*)d_in[i]; break;
            case 5*48*32:     agg_W   = (const float*)d_in[i]; break;
            case 5*48:        agg_b   = (const float*)d_in[i]; break;
            case 144*48:      ipw     = (const float*)d_in[i]; break;
            case 144:         ipb     = (const float*)d_in[i]; break;
            case 48*48:       out_w   = (const float*)d_in[i]; break;
            case 48:          out_b   = (const float*)d_in[i]; break;
            case 272*96:      extra_w = (const float*)d_in[i]; break;
            case 272:         extra_b = (const float*)d_in[i]; break;
            default: break;
        }
    }
    float* out = (float*)d_out;

    prep_kernel<<<17, PREP_T>>>(agg_W, agg_b, ipw, ipb, out_w, extra_w);

    const int smem_bytes = SM_FLOATS * (int)sizeof(float);   // 170496
    cudaFuncSetAttribute(main_kernel, cudaFuncAttributeMaxDynamicSharedMemorySize, smem_bytes);
    main_kernel<<<NBLOCKS, THREADS, smem_bytes>>>(x, extra_b, out_b, out);
}

// round 5
// speedup vs baseline: 1.7269x; 1.3688x over previous
#include <cuda_runtime.h>
#include <cuda_bf16.h>
#include <cstdint>

#define AA 5
#define THREADS 512
#define ROWS_PB 160
#define GROUPS_PB 32
#define NBLOCKS 4096

// ---------------- precomputed fused weights (packed bf16x2 hi/lo) ----------
__device__ uint32_t g_Wqk_hp[AA][96][16];
__device__ uint32_t g_Wqk_lp[AA][96][16];
__device__ float    g_bqk  [AA][96];
__device__ uint32_t g_Wvo_hp[AA][96][16];
__device__ uint32_t g_Wvo_lp[AA][96][16];
__device__ float    g_bvo  [AA][96];
__device__ uint32_t g_EW_hp[272][48];
__device__ uint32_t g_EW_lp[272][48];

__device__ __forceinline__ void split_bf16(float v, float& h, float& l) {
    h = __bfloat162float(__float2bfloat16_rn(v));
    l = v - h;
}

// pack: lo_e -> bits[15:0], hi_e -> bits[31:16]
__device__ __forceinline__ uint32_t packbf(float lo_e, float hi_e) {
    uint32_t r;
    asm("cvt.rn.bf16x2.f32 %0, %1, %2;" : "=r"(r) : "f"(hi_e), "f"(lo_e));
    return r;
}

__device__ __forceinline__ void mma16(float* d,
                                      uint32_t a0, uint32_t a1, uint32_t a2, uint32_t a3,
                                      uint32_t b0, uint32_t b1) {
    asm volatile("mma.sync.aligned.m16n8k16.row.col.f32.bf16.bf16.f32 "
                 "{%0,%1,%2,%3}, {%4,%5,%6,%7}, {%8,%9}, {%0,%1,%2,%3};"
                 : "+f"(d[0]), "+f"(d[1]), "+f"(d[2]), "+f"(d[3])
                 : "r"(a0), "r"(a1), "r"(a2), "r"(a3), "r"(b0), "r"(b1));
}

// ---------------------------- prep kernel ----------------------------------
#define PREP_T 256
__global__ void prep_kernel(const float* __restrict__ agg_W,
                            const float* __restrict__ agg_b,
                            const float* __restrict__ ipw,
                            const float* __restrict__ ipb,
                            const float* __restrict__ out_w,
                            const float* __restrict__ extra_w)
{
    int bid = blockIdx.x;
    if (bid < AA) {
        int a = bid;
        for (int o = threadIdx.x; o < 96*16; o += PREP_T) {
            int j = o >> 4, w = o & 15;
            float acc0 = 0.f, acc1 = 0.f;
            for (int e = 0; e < 48; e++) {
                float wv = ipw[j*48+e];
                acc0 += wv * agg_W[(a*48+e)*32 + 2*w];
                acc1 += wv * agg_W[(a*48+e)*32 + 2*w+1];
            }
            float h0,l0,h1,l1;
            split_bf16(acc0, h0, l0); split_bf16(acc1, h1, l1);
            g_Wqk_hp[a][j][w] = packbf(h0, h1);
            g_Wqk_lp[a][j][w] = packbf(l0, l1);
        }
        for (int j = threadIdx.x; j < 96; j += PREP_T) {
            float acc = ipb[j];
            for (int e = 0; e < 48; e++)
                acc += ipw[j*48+e] * agg_b[a*48+e];
            g_bqk[a][j] = acc;
        }
    } else if (bid < AA + 2*AA) {
        int a = (bid - AA) >> 1;
        int h = (bid - AA) & 1;
        __shared__ float Wv[24][32];
        __shared__ float bv[24];
        for (int o = threadIdx.x; o < 24*32; o += PREP_T) {
            int d = o >> 5, c = o & 31;
            int row = 96 + h*24 + d;
            float acc = 0.f;
            for (int e = 0; e < 48; e++)
                acc += ipw[row*48+e] * agg_W[(a*48+e)*32 + c];
            Wv[d][c] = acc;
        }
        for (int d = threadIdx.x; d < 24; d += PREP_T) {
            int row = 96 + h*24 + d;
            float acc = ipb[row];
            for (int e = 0; e < 48; e++)
                acc += ipw[row*48+e] * agg_b[a*48+e];
            bv[d] = acc;
        }
        __syncthreads();
        for (int o = threadIdx.x; o < 48*16; o += PREP_T) {
            int e = o >> 4, w = o & 15;
            float acc0 = 0.f, acc1 = 0.f;
            for (int d = 0; d < 24; d++) {
                float ow = out_w[e*48 + h*24 + d];
                acc0 += Wv[d][2*w]   * ow;
                acc1 += Wv[d][2*w+1] * ow;
            }
            float h0,l0,h1,l1;
            split_bf16(acc0, h0, l0); split_bf16(acc1, h1, l1);
            g_Wvo_hp[a][h*48 + e][w] = packbf(h0, h1);
            g_Wvo_lp[a][h*48 + e][w] = packbf(l0, l1);
        }
        for (int e = threadIdx.x; e < 48; e += PREP_T) {
            float acc = 0.f;
            for (int d = 0; d < 24; d++)
                acc += bv[d] * out_w[e*48 + h*24 + d];
            g_bvo[a][h*48 + e] = acc;
        }
    } else {
        int part = bid - 3*AA;                // 0 or 1
        int beg = part * (272*48/2);
        int end = beg + (272*48/2);
        for (int o = beg + threadIdx.x; o < end; o += PREP_T) {
            int r = o / 48, w = o % 48;
            float v0 = extra_w[r*96 + 2*w];
            float v1 = extra_w[r*96 + 2*w+1];
            float h0,l0,h1,l1;
            split_bf16(v0, h0, l0); split_bf16(v1, h1, l1);
            g_EW_hp[r][w] = packbf(h0, h1);
            g_EW_lp[r][w] = packbf(l0, l1);
        }
    }
}

// ---------------------------- main kernel ----------------------------------
// Shared layout (32-bit words):
//   xsh/xsl : 160 x 18  (packed bf16x2 x slices; phase5 reuses as xe 32 x 50)
//   ws      : 12800     (qk/vo: 2 sets of [hi 96x18][lo 96x18]; extra: [hi 128x50][lo 128x50])
//   qk      : 160 x 98  fp32 (GEMM results: qk then vo)
//   pb      : 32 x 50   fp32 (softmax probs)
#define XSP 18
#define QKP 98
#define XEP 50
#define SM_XSH 0
#define SM_XSL 2880
#define SM_WS  5760
#define WLO    (96*XSP)          // 1728
#define WSET   (2*96*XSP)        // 3456
#define WE_LO  6400
#define SM_QK  18560
#define SM_PB  34240
#define SM_WORDS 35840           // 143360 bytes

__device__ __forceinline__ long row_xoff(int r)
{
    int a  = (r >> 12) % 5;
    int tx = (r / 20480) * 4096 + (r & 4095);
    return (long)tx * 256 + a * 32;
}

__global__ void __launch_bounds__(THREADS, 1)
main_kernel(const float* __restrict__ x,
            const float* __restrict__ extra_b,
            const float* __restrict__ out_b,
            float* __restrict__ out)
{
    extern __shared__ float sm[];
    uint32_t* smw = (uint32_t*)sm;
    uint32_t* xsh = smw + SM_XSH;
    uint32_t* xsl = smw + SM_XSL;
    uint32_t* ws  = smw + SM_WS;
    float*    qk  = sm  + SM_QK;
    float*    pb  = sm  + SM_PB;

    const int tid  = threadIdx.x;
    const int lane = tid & 31;
    const int warp = tid >> 5;       // 0..15
    const int g4   = lane >> 2;
    const int t4   = lane & 3;
    const int z    = tid & 15;
    const int t0   = tid >> 4;       // 0..31

    const int r0    = blockIdx.x * ROWS_PB;
    const int m0tok = blockIdx.x * GROUPS_PB;

    const int  blk4k = r0 >> 12;
    const int  a_lo  = blk4k % 5;
    const int  Bnd   = (blk4k + 1) << 12;
    const bool has_b = (r0 + ROWS_PB) > Bnd;
    const int  a_hi  = has_b ? ((a_lo + 1) % 5) : a_lo;

    // ---- phase 0: stage x rows (split + packed) + qk weights ---------------
    for (int i = tid; i < 1280; i += THREADS) {        // 160 rows * 8 float4
        int row = i >> 3, q = i & 7;
        const float4 v = *(const float4*)(x + row_xoff(r0 + row) + q*4);
        float h0,l0,h1,l1,h2,l2,h3,l3;
        split_bf16(v.x, h0, l0); split_bf16(v.y, h1, l1);
        split_bf16(v.z, h2, l2); split_bf16(v.w, h3, l3);
        *(uint2*)&xsh[row*XSP + q*2] = make_uint2(packbf(h0,h1), packbf(h2,h3));
        *(uint2*)&xsl[row*XSP + q*2] = make_uint2(packbf(l0,l1), packbf(l2,l3));
    }
    for (int i = tid; i < 96*16; i += THREADS) {
        int j = i >> 4, w = i & 15;
        ws[j*XSP + w]       = g_Wqk_hp[a_lo][j][w];
        ws[WLO + j*XSP + w] = g_Wqk_lp[a_lo][j][w];
        if (has_b) {
            ws[WSET + j*XSP + w]       = g_Wqk_hp[a_hi][j][w];
            ws[WSET + WLO + j*XSP + w] = g_Wqk_lp[a_hi][j][w];
        }
    }
    __syncthreads();

    // ---- phase 1: GEMM qk : D[160x96] --------------------------------------
    #pragma unroll 1
    for (int task = warp; task < 60; task += 16) {
        int mt = task / 6, ng = task % 6;
        bool hiset = has_b && (r0 + mt*16) >= Bnd;
        const uint32_t* wsb = ws + (hiset ? WSET : 0);
        int a_t = hiset ? a_hi : a_lo;
        int arow = mt*16 + g4;

        float acc[2][4];
        #pragma unroll
        for (int nj = 0; nj < 2; nj++)
            #pragma unroll
            for (int q = 0; q < 4; q++) acc[nj][q] = 0.f;

        #pragma unroll
        for (int ks = 0; ks < 2; ks++) {
            const uint32_t* aph = xsh + arow*XSP + ks*8 + t4;
            const uint32_t* apl = xsl + arow*XSP + ks*8 + t4;
            uint32_t ah0=aph[0], ah2=aph[4], ah1=aph[8*XSP], ah3=aph[8*XSP+4];
            uint32_t al0=apl[0], al2=apl[4], al1=apl[8*XSP], al3=apl[8*XSP+4];
            #pragma unroll
            for (int nj = 0; nj < 2; nj++) {
                const uint32_t* bp = wsb + (ng*16 + nj*8 + g4)*XSP + ks*8 + t4;
                uint32_t bh0 = bp[0], bh1 = bp[4];
                uint32_t bl0 = bp[WLO], bl1 = bp[WLO+4];
                mma16(acc[nj], ah0,ah1,ah2,ah3, bh0,bh1);
                mma16(acc[nj], ah0,ah1,ah2,ah3, bl0,bl1);
                mma16(acc[nj], al0,al1,al2,al3, bh0,bh1);
            }
        }
        #pragma unroll
        for (int nj = 0; nj < 2; nj++) {
            int j0 = ng*16 + nj*8 + 2*t4;
            float b0 = g_bqk[a_t][j0], b1 = g_bqk[a_t][j0+1];
            *(float2*)&qk[(mt*16+g4  )*QKP + j0] =
                make_float2(acc[nj][0]+b0, acc[nj][1]+b1);
            *(float2*)&qk[(mt*16+g4+8)*QKP + j0] =
                make_float2(acc[nj][2]+b0, acc[nj][3]+b1);
        }
    }
    __syncthreads();

    // ---- phase 2: softmax + restage ws with vo weights ---------------------
    if (z < 10) {
        int h = z / 5, ii = z % 5;
        int g = t0;
        const float* gb = qk + g*5*QKP;
        float qreg[24];
        const float* qp = gb + ii*QKP + h*24;
        #pragma unroll
        for (int d = 0; d < 24; d++) qreg[d] = qp[d];
        float s[5]; float mx = -1e30f;
        #pragma unroll
        for (int j = 0; j < 5; j++) {
            float a = 0.f;
            const float* kp = gb + j*QKP + 48 + h*24;
            #pragma unroll
            for (int d = 0; d < 24; d++) a = fmaf(qreg[d], kp[d], a);
            s[j] = a * 0.20412414523193154f;
            mx = fmaxf(mx, s[j]);
        }
        float sum = 0.f;
        #pragma unroll
        for (int j = 0; j < 5; j++) { s[j] = __expf(s[j]-mx); sum += s[j]; }
        float inv = 1.f / sum;
        #pragma unroll
        for (int j = 0; j < 5; j++) pb[g*50 + z*5 + j] = s[j]*inv;
    }
    for (int i = tid; i < 96*16; i += THREADS) {
        int j = i >> 4, w = i & 15;
        ws[j*XSP + w]       = g_Wvo_hp[a_lo][j][w];
        ws[WLO + j*XSP + w] = g_Wvo_lp[a_lo][j][w];
        if (has_b) {
            ws[WSET + j*XSP + w]       = g_Wvo_hp[a_hi][j][w];
            ws[WSET + WLO + j*XSP + w] = g_Wvo_lp[a_hi][j][w];
        }
    }
    __syncthreads();

    // ---- phase 3: GEMM vo (overwrites qk buffer) ---------------------------
    #pragma unroll 1
    for (int task = warp; task < 60; task += 16) {
        int mt = task / 6, ng = task % 6;
        bool hiset = has_b && (r0 + mt*16) >= Bnd;
        const uint32_t* wsb = ws + (hiset ? WSET : 0);
        int a_t = hiset ? a_hi : a_lo;
        int arow = mt*16 + g4;

        float acc[2][4];
        #pragma unroll
        for (int nj = 0; nj < 2; nj++)
            #pragma unroll
            for (int q = 0; q < 4; q++) acc[nj][q] = 0.f;

        #pragma unroll
        for (int ks = 0; ks < 2; ks++) {
            const uint32_t* aph = xsh + arow*XSP + ks*8 + t4;
            const uint32_t* apl = xsl + arow*XSP + ks*8 + t4;
            uint32_t ah0=aph[0], ah2=aph[4], ah1=aph[8*XSP], ah3=aph[8*XSP+4];
            uint32_t al0=apl[0], al2=apl[4], al1=apl[8*XSP], al3=apl[8*XSP+4];
            #pragma unroll
            for (int nj = 0; nj < 2; nj++) {
                const uint32_t* bp = wsb + (ng*16 + nj*8 + g4)*XSP + ks*8 + t4;
                uint32_t bh0 = bp[0], bh1 = bp[4];
                uint32_t bl0 = bp[WLO], bl1 = bp[WLO+4];
                mma16(acc[nj], ah0,ah1,ah2,ah3, bh0,bh1);
                mma16(acc[nj], ah0,ah1,ah2,ah3, bl0,bl1);
                mma16(acc[nj], al0,al1,al2,al3, bh0,bh1);
            }
        }
        #pragma unroll
        for (int nj = 0; nj < 2; nj++) {
            int j0 = ng*16 + nj*8 + 2*t4;
            float b0 = g_bvo[a_t][j0], b1 = g_bvo[a_t][j0+1];
            *(float2*)&qk[(mt*16+g4  )*QKP + j0] =
                make_float2(acc[nj][0]+b0, acc[nj][1]+b1);
            *(float2*)&qk[(mt*16+g4+8)*QKP + j0] =
                make_float2(acc[nj][2]+b0, acc[nj][3]+b1);
        }
    }
    __syncthreads();

    // ---- phase 4: combine -> out cols [0,240); stage xe (split+packed) ----
    {
        int g = t0;
        const float* pg = pb + g*50;
        const float* vg = qk + g*5*QKP;
        float pc[10];
        int icur = -1;
        #pragma unroll
        for (int m = 0; m < 15; m++) {
            int col = z + 16*m;
            int i = col / 48;
            if (i != icur) {
                icur = i;
                #pragma unroll
                for (int hj = 0; hj < 10; hj++)
                    pc[hj] = pg[(hj/5*5 + i)*5 + (hj%5)];
            }
            int e = col - i*48;
            float acc = out_b[e];
            #pragma unroll
            for (int hj = 0; hj < 10; hj++)
                acc = fmaf(pc[hj], vg[(hj%5)*QKP + (hj/5)*48 + e], acc);
            out[(long)(m0tok+g)*512 + col] = acc;
        }
    }
    // xe: 32 tokens x 96 feats -> 48 packed words, pitch 50
    for (int i = tid; i < 768; i += THREADS) {          // 32 * 24 float4
        int tok = i / 24, q = i % 24;
        const float4 v = *(const float4*)(x + (long)(m0tok + tok)*256 + 160 + q*4);
        float h0,l0,h1,l1,h2,l2,h3,l3;
        split_bf16(v.x, h0, l0); split_bf16(v.y, h1, l1);
        split_bf16(v.z, h2, l2); split_bf16(v.w, h3, l3);
        *(uint2*)&xsh[tok*XEP + q*2] = make_uint2(packbf(h0,h1), packbf(h2,h3));
        *(uint2*)&xsl[tok*XEP + q*2] = make_uint2(packbf(l0,l1), packbf(l2,l3));
    }

    // ---- phase 5: extra GEMM [32x96] @ [96 x 272], chunks of 128 cols ------
    int u0 = 0;
    #pragma unroll 1
    for (int chunk = 0; chunk < 3; chunk++) {
        int R = (chunk < 2) ? 128 : 16;
        if (chunk) __syncthreads();
        for (int i = tid; i < R*48; i += THREADS) {
            int r = i / 48, w = i % 48;
            ws[r*XEP + w]         = g_EW_hp[u0 + r][w];
            ws[WE_LO + r*XEP + w] = g_EW_lp[u0 + r][w];
        }
        __syncthreads();

        int tasks = 2 * (R >> 4);                        // 16 or 2
        #pragma unroll 1
        for (int t = warp; t < tasks; t += 16) {
            int mt = t & 1, ng = t >> 1;
            float acc[2][4];
            #pragma unroll
            for (int nj = 0; nj < 2; nj++)
                #pragma unroll
                for (int q = 0; q < 4; q++) acc[nj][q] = 0.f;

            #pragma unroll
            for (int ks = 0; ks < 6; ks++) {
                const uint32_t* aph = xsh + (mt*16 + g4)*XEP + ks*8 + t4;
                const uint32_t* apl = xsl + (mt*16 + g4)*XEP + ks*8 + t4;
                uint32_t ah0=aph[0], ah2=aph[4], ah1=aph[8*XEP], ah3=aph[8*XEP+4];
                uint32_t al0=apl[0], al2=apl[4], al1=apl[8*XEP], al3=apl[8*XEP+4];
                #pragma unroll
                for (int nj = 0; nj < 2; nj++) {
                    const uint32_t* bp = ws + (ng*16 + nj*8 + g4)*XEP + ks*8 + t4;
                    uint32_t bh0 = bp[0], bh1 = bp[4];
                    uint32_t bl0 = bp[WE_LO], bl1 = bp[WE_LO+4];
                    mma16(acc[nj], ah0,ah1,ah2,ah3, bh0,bh1);
                    mma16(acc[nj], ah0,ah1,ah2,ah3, bl0,bl1);
                    mma16(acc[nj], al0,al1,al2,al3, bh0,bh1);
                }
            }
            #pragma unroll
            for (int nj = 0; nj < 2; nj++) {
                int u = u0 + ng*16 + nj*8 + 2*t4;
                float bb0 = extra_b[u], bb1 = extra_b[u+1];
                long tok = m0tok + mt*16 + g4;
                *(float2*)&out[tok*512 + 240 + u] =
                    make_float2(acc[nj][0]+bb0, acc[nj][1]+bb1);
                *(float2*)&out[(tok+8)*512 + 240 + u] =
                    make_float2(acc[nj][2]+bb0, acc[nj][3]+bb1);
            }
        }
        u0 += R;
    }
}

extern "C" void kernel_launch(void* const* d_in, const int* in_sizes, int n_in,
                              void* d_out, int out_size)
{
    const float *x=0, *agg_W=0, *agg_b=0, *ipw=0, *ipb=0, *out_w=0, *out_b=0, *extra_w=0, *extra_b=0;
    for (int i = 0; i < n_in; i++) {
        switch (in_sizes[i]) {
            case 32*4096*256: x       = (const float*)d_in[i]; break;
            case 5*48*32:     agg_W   = (const float*)d_in[i]; break;
            case 5*48:        agg_b   = (const float*)d_in[i]; break;
            case 144*48:      ipw     = (const float*)d_in[i]; break;
            case 144:         ipb     = (const float*)d_in[i]; break;
            case 48*48:       out_w   = (const float*)d_in[i]; break;
            case 48:          out_b   = (const float*)d_in[i]; break;
            case 272*96:      extra_w = (const float*)d_in[i]; break;
            case 272:         extra_b = (const float*)d_in[i]; break;
            default: break;
        }
    }
    float* out = (float*)d_out;

    prep_kernel<<<17, PREP_T>>>(agg_W, agg_b, ipw, ipb, out_w, extra_w);

    const int smem_bytes = SM_WORDS * 4;   // 143360
    cudaFuncSetAttribute(main_kernel, cudaFuncAttributeMaxDynamicSharedMemorySize, smem_bytes);
    main_kernel<<<NBLOCKS, THREADS, smem_bytes>>>(x, extra_b, out_b, out);
}

// round 6
// speedup vs baseline: 2.1199x; 1.2276x over previous
#include <cuda_runtime.h>
#include <cuda_bf16.h>
#include <cstdint>

#define AA 5
#define THREADS 512
#define ROWS_PB 160
#define GROUPS_PB 32
#define NBLOCKS 4096

// ---------------- precomputed fused weights (packed bf16x2 hi/lo) ----------
__device__ uint32_t g_Wqk_hp[AA][96][16];
__device__ uint32_t g_Wqk_lp[AA][96][16];
__device__ float    g_bqk  [AA][96];
__device__ uint32_t g_Wvo_hp[AA][96][16];
__device__ uint32_t g_Wvo_lp[AA][96][16];
__device__ float    g_bvo  [AA][96];
__device__ uint32_t g_EW_hp[272][48];
__device__ uint32_t g_EW_lp[272][48];

__device__ __forceinline__ void split_bf16(float v, float& h, float& l) {
    h = __bfloat162float(__float2bfloat16_rn(v));
    l = v - h;
}

// pack: lo_e -> bits[15:0], hi_e -> bits[31:16]
__device__ __forceinline__ uint32_t packbf(float lo_e, float hi_e) {
    uint32_t r;
    asm("cvt.rn.bf16x2.f32 %0, %1, %2;" : "=r"(r) : "f"(hi_e), "f"(lo_e));
    return r;
}

__device__ __forceinline__ void mma16(float* d,
                                      uint32_t a0, uint32_t a1, uint32_t a2, uint32_t a3,
                                      uint32_t b0, uint32_t b1) {
    asm volatile("mma.sync.aligned.m16n8k16.row.col.f32.bf16.bf16.f32 "
                 "{%0,%1,%2,%3}, {%4,%5,%6,%7}, {%8,%9}, {%0,%1,%2,%3};"
                 : "+f"(d[0]), "+f"(d[1]), "+f"(d[2]), "+f"(d[3])
                 : "r"(a0), "r"(a1), "r"(a2), "r"(a3), "r"(b0), "r"(b1));
}

// ---------------------------- prep kernel ----------------------------------
#define PREP_T 256
__global__ void prep_kernel(const float* __restrict__ agg_W,
                            const float* __restrict__ agg_b,
                            const float* __restrict__ ipw,
                            const float* __restrict__ ipb,
                            const float* __restrict__ out_w,
                            const float* __restrict__ extra_w)
{
    int bid = blockIdx.x;
    if (bid < AA) {
        int a = bid;
        for (int o = threadIdx.x; o < 96*16; o += PREP_T) {
            int j = o >> 4, w = o & 15;
            float acc0 = 0.f, acc1 = 0.f;
            for (int e = 0; e < 48; e++) {
                float wv = ipw[j*48+e];
                acc0 += wv * agg_W[(a*48+e)*32 + 2*w];
                acc1 += wv * agg_W[(a*48+e)*32 + 2*w+1];
            }
            float h0,l0,h1,l1;
            split_bf16(acc0, h0, l0); split_bf16(acc1, h1, l1);
            g_Wqk_hp[a][j][w] = packbf(h0, h1);
            g_Wqk_lp[a][j][w] = packbf(l0, l1);
        }
        for (int j = threadIdx.x; j < 96; j += PREP_T) {
            float acc = ipb[j];
            for (int e = 0; e < 48; e++)
                acc += ipw[j*48+e] * agg_b[a*48+e];
            g_bqk[a][j] = acc;
        }
    } else if (bid < AA + 2*AA) {
        int a = (bid - AA) >> 1;
        int h = (bid - AA) & 1;
        __shared__ float Wv[24][32];
        __shared__ float bv[24];
        for (int o = threadIdx.x; o < 24*32; o += PREP_T) {
            int d = o >> 5, c = o & 31;
            int row = 96 + h*24 + d;
            float acc = 0.f;
            for (int e = 0; e < 48; e++)
                acc += ipw[row*48+e] * agg_W[(a*48+e)*32 + c];
            Wv[d][c] = acc;
        }
        for (int d = threadIdx.x; d < 24; d += PREP_T) {
            int row = 96 + h*24 + d;
            float acc = ipb[row];
            for (int e = 0; e < 48; e++)
                acc += ipw[row*48+e] * agg_b[a*48+e];
            bv[d] = acc;
        }
        __syncthreads();
        for (int o = threadIdx.x; o < 48*16; o += PREP_T) {
            int e = o >> 4, w = o & 15;
            float acc0 = 0.f, acc1 = 0.f;
            for (int d = 0; d < 24; d++) {
                float ow = out_w[e*48 + h*24 + d];
                acc0 += Wv[d][2*w]   * ow;
                acc1 += Wv[d][2*w+1] * ow;
            }
            float h0,l0,h1,l1;
            split_bf16(acc0, h0, l0); split_bf16(acc1, h1, l1);
            g_Wvo_hp[a][h*48 + e][w] = packbf(h0, h1);
            g_Wvo_lp[a][h*48 + e][w] = packbf(l0, l1);
        }
        for (int e = threadIdx.x; e < 48; e += PREP_T) {
            float acc = 0.f;
            for (int d = 0; d < 24; d++)
                acc += bv[d] * out_w[e*48 + h*24 + d];
            g_bvo[a][h*48 + e] = acc;
        }
    } else {
        int part = bid - 3*AA;                // 0 or 1
        int beg = part * (272*48/2);
        int end = beg + (272*48/2);
        for (int o = beg + threadIdx.x; o < end; o += PREP_T) {
            int r = o / 48, w = o % 48;
            float v0 = extra_w[r*96 + 2*w];
            float v1 = extra_w[r*96 + 2*w+1];
            float h0,l0,h1,l1;
            split_bf16(v0, h0, l0); split_bf16(v1, h1, l1);
            g_EW_hp[r][w] = packbf(h0, h1);
            g_EW_lp[r][w] = packbf(l0, l1);
        }
    }
}

// ---------------------------- main kernel ----------------------------------
// Shared layout (32-bit words):
//   xsh/xsl : 160 x 20  packed bf16x2 x slices (conflict-free pitch)
//             phase5 reuses as xe 32 x 52
//   ws      : 15360  qk|vo unified weights: 2 sets of [hi 192x20][lo 192x20]
//             phase5 reuses as extra hi 272 x 52
//   qk      : fp32 GEMM results, row r at r*200 + (r/5)*8 (group stride 1008)
//             phase5 reuses as extra lo 272 x 52
//   pb      : 32 x 50 fp32 softmax probs
#define XSP 20
#define QKP 200
#define XEP 52
#define SM_XSH 0
#define SM_XSL 3200
#define SM_WS  6400
#define WLO    3840              // 192*20
#define WSET   7680
#define SM_QK  21760
#define SM_PB  54000
#define SM_WORDS 55600           // 222400 bytes

__device__ __forceinline__ long row_xoff(int r)
{
    int a  = (r >> 12) % 5;
    int tx = (r / 20480) * 4096 + (r & 4095);
    return (long)tx * 256 + a * 32;
}

__global__ void __launch_bounds__(THREADS, 1)
main_kernel(const float* __restrict__ x,
            const float* __restrict__ extra_b,
            const float* __restrict__ out_b,
            float* __restrict__ out)
{
    extern __shared__ float sm[];
    uint32_t* smw = (uint32_t*)sm;
    uint32_t* xsh = smw + SM_XSH;
    uint32_t* xsl = smw + SM_XSL;
    uint32_t* ws  = smw + SM_WS;
    float*    qk  = sm  + SM_QK;
    uint32_t* qkw = smw + SM_QK;
    float*    pb  = sm  + SM_PB;

    const int tid  = threadIdx.x;
    const int lane = tid & 31;
    const int warp = tid >> 5;       // 0..15
    const int g4   = lane >> 2;
    const int t4   = lane & 3;
    const int z    = tid & 15;
    const int t0   = tid >> 4;       // 0..31

    const int r0    = blockIdx.x * ROWS_PB;
    const int m0tok = blockIdx.x * GROUPS_PB;

    const int  blk4k = r0 >> 12;
    const int  a_lo  = blk4k % 5;
    const int  Bnd   = (blk4k + 1) << 12;
    const bool has_b = (r0 + ROWS_PB) > Bnd;
    const int  a_hi  = has_b ? ((a_lo + 1) % 5) : a_lo;

    // ---- phase 0: stage x rows (split + packed) + unified qk|vo weights ----
    for (int i = tid; i < 1280; i += THREADS) {        // 160 rows * 8 float4
        int row = i >> 3, q = i & 7;
        const float4 v = *(const float4*)(x + row_xoff(r0 + row) + q*4);
        float h0,l0,h1,l1,h2,l2,h3,l3;
        split_bf16(v.x, h0, l0); split_bf16(v.y, h1, l1);
        split_bf16(v.z, h2, l2); split_bf16(v.w, h3, l3);
        *(uint2*)&xsh[row*XSP + q*2] = make_uint2(packbf(h0,h1), packbf(h2,h3));
        *(uint2*)&xsl[row*XSP + q*2] = make_uint2(packbf(l0,l1), packbf(l2,l3));
    }
    for (int i = tid; i < 192*16; i += THREADS) {
        int j = i >> 4, w = i & 15;
        uint32_t h0 = (j < 96) ? g_Wqk_hp[a_lo][j][w] : g_Wvo_hp[a_lo][j-96][w];
        uint32_t l0 = (j < 96) ? g_Wqk_lp[a_lo][j][w] : g_Wvo_lp[a_lo][j-96][w];
        ws[j*XSP + w]       = h0;
        ws[WLO + j*XSP + w] = l0;
        if (has_b) {
            uint32_t h1 = (j < 96) ? g_Wqk_hp[a_hi][j][w] : g_Wvo_hp[a_hi][j-96][w];
            uint32_t l1 = (j < 96) ? g_Wqk_lp[a_hi][j][w] : g_Wvo_lp[a_hi][j-96][w];
            ws[WSET + j*XSP + w]       = h1;
            ws[WSET + WLO + j*XSP + w] = l1;
        }
    }
    __syncthreads();

    // ---- phase 1: unified GEMM D[160 x 192] (qk cols 0-95, vo cols 96-191) -
    #pragma unroll 1
    for (int task = warp; task < 40; task += 16) {
        int mt = task >> 2, ng = task & 3;               // ng: 48-col group
        bool hiset = has_b && (r0 + mt*16) >= Bnd;
        const uint32_t* wsb = ws + (hiset ? WSET : 0);
        int a_t = hiset ? a_hi : a_lo;
        int arow = mt*16 + g4;

        // A fragments (held in regs across all 6 nj)
        uint32_t ah[2][4], al[2][4];
        #pragma unroll
        for (int ks = 0; ks < 2; ks++) {
            const uint32_t* aph = xsh + arow*XSP + ks*8 + t4;
            const uint32_t* apl = xsl + arow*XSP + ks*8 + t4;
            ah[ks][0]=aph[0]; ah[ks][2]=aph[4];
            ah[ks][1]=aph[8*XSP]; ah[ks][3]=aph[8*XSP+4];
            al[ks][0]=apl[0]; al[ks][2]=apl[4];
            al[ks][1]=apl[8*XSP]; al[ks][3]=apl[8*XSP+4];
        }

        float acc[6][4];
        #pragma unroll
        for (int nj = 0; nj < 6; nj++)
            #pragma unroll
            for (int q = 0; q < 4; q++) acc[nj][q] = 0.f;

        #pragma unroll
        for (int ks = 0; ks < 2; ks++) {
            #pragma unroll
            for (int nj = 0; nj < 6; nj++) {
                const uint32_t* bp = wsb + (ng*48 + nj*8 + g4)*XSP + ks*8 + t4;
                uint32_t bh0 = bp[0], bh1 = bp[4];
                uint32_t bl0 = bp[WLO], bl1 = bp[WLO+4];
                mma16(acc[nj], ah[ks][0],ah[ks][1],ah[ks][2],ah[ks][3], bh0,bh1);
                mma16(acc[nj], ah[ks][0],ah[ks][1],ah[ks][2],ah[ks][3], bl0,bl1);
                mma16(acc[nj], al[ks][0],al[ks][1],al[ks][2],al[ks][3], bh0,bh1);
            }
        }

        int R0 = mt*16 + g4;
        int R1 = R0 + 8;
        int off0 = R0*QKP + (R0/5)*8;
        int off1 = R1*QKP + (R1/5)*8;
        const float* bias = (ng < 2) ? g_bqk[a_t] : g_bvo[a_t];
        int cb = (ng & 1) * 48;
        #pragma unroll
        for (int nj = 0; nj < 6; nj++) {
            int jj = nj*8 + 2*t4;
            float b0 = bias[cb + jj], b1 = bias[cb + jj + 1];
            int col = ng*48 + jj;
            *(float2*)&qk[off0 + col] = make_float2(acc[nj][0]+b0, acc[nj][1]+b1);
            *(float2*)&qk[off1 + col] = make_float2(acc[nj][2]+b0, acc[nj][3]+b1);
        }
    }
    __syncthreads();

    // ---- phase 2: softmax + stage xe and extra-hi weights ------------------
    if (z < 10) {
        int h = z / 5, ii = z % 5;
        int g = t0;
        const float* gb = qk + g*1008;
        float qreg[24];
        const float* qp = gb + ii*QKP + h*24;
        #pragma unroll
        for (int d = 0; d < 24; d++) qreg[d] = qp[d];
        float s[5]; float mx = -1e30f;
        #pragma unroll
        for (int j = 0; j < 5; j++) {
            float a = 0.f;
            const float* kp = gb + j*QKP + 48 + h*24;
            #pragma unroll
            for (int d = 0; d < 24; d++) a = fmaf(qreg[d], kp[d], a);
            s[j] = a * 0.20412414523193154f;
            mx = fmaxf(mx, s[j]);
        }
        float sum = 0.f;
        #pragma unroll
        for (int j = 0; j < 5; j++) { s[j] = __expf(s[j]-mx); sum += s[j]; }
        float inv = 1.f / sum;
        #pragma unroll
        for (int j = 0; j < 5; j++) pb[g*50 + z*5 + j] = s[j]*inv;
    }
    // xe: 32 tokens x 96 feats -> 48 packed words, pitch 52 (xs region dead)
    for (int i = tid; i < 768; i += THREADS) {          // 32 * 24 float4
        int tok = i / 24, q = i % 24;
        const float4 v = *(const float4*)(x + (long)(m0tok + tok)*256 + 160 + q*4);
        float h0,l0,h1,l1,h2,l2,h3,l3;
        split_bf16(v.x, h0, l0); split_bf16(v.y, h1, l1);
        split_bf16(v.z, h2, l2); split_bf16(v.w, h3, l3);
        *(uint2*)&xsh[tok*XEP + q*2] = make_uint2(packbf(h0,h1), packbf(h2,h3));
        *(uint2*)&xsl[tok*XEP + q*2] = make_uint2(packbf(l0,l1), packbf(l2,l3));
    }
    // extra-w hi into ws region (dead after GEMM): 272 rows x 48 words, pitch 52
    for (int i = tid; i < 272*48; i += THREADS) {
        int r = i / 48, w = i % 48;
        ws[r*XEP + w] = g_EW_hp[r][w];
    }
    __syncthreads();

    // ---- phase 3: combine -> out cols [0,240) ------------------------------
    {
        int g = t0;
        const float* pg = pb + g*50;
        const float* vg = qk + g*1008 + 96;
        float pc[50];
        #pragma unroll
        for (int k = 0; k < 50; k++) pc[k] = pg[k];
        #pragma unroll
        for (int eidx = 0; eidx < 3; eidx++) {
            int e = z + 16*eidx;
            float vr[10];
            #pragma unroll
            for (int h = 0; h < 2; h++)
                #pragma unroll
                for (int j = 0; j < 5; j++)
                    vr[h*5+j] = vg[j*QKP + h*48 + e];
            float ob = out_b[e];
            #pragma unroll
            for (int i = 0; i < 5; i++) {
                float acc = ob;
                #pragma unroll
                for (int h = 0; h < 2; h++)
                    #pragma unroll
                    for (int j = 0; j < 5; j++)
                        acc = fmaf(pc[(h*5+i)*5+j], vr[h*5+j], acc);
                out[(long)(m0tok+g)*512 + i*48 + e] = acc;
            }
        }
    }
    __syncthreads();

    // ---- phase 4: stage extra-w lo into qk region (dead after combine) -----
    for (int i = tid; i < 272*48; i += THREADS) {
        int r = i / 48, w = i % 48;
        qkw[r*XEP + w] = g_EW_lp[r][w];
    }
    __syncthreads();

    // ---- phase 5: extra GEMM [32 x 96] @ [96 x 272] -------------------------
    {
        int mt = warp >> 3;          // warps 0-7: mt0, 8-15: mt1
        int ng = warp & 7;           // 32-col group: cols ng*32 .. +31

        // A fragments for this warp's 16 token-rows, all 6 k-steps, in regs
        uint32_t Ah[6][4], Al[6][4];
        #pragma unroll
        for (int ks = 0; ks < 6; ks++) {
            const uint32_t* aph = xsh + (mt*16 + g4)*XEP + ks*8 + t4;
            const uint32_t* apl = xsl + (mt*16 + g4)*XEP + ks*8 + t4;
            Ah[ks][0]=aph[0]; Ah[ks][2]=aph[4];
            Ah[ks][1]=aph[8*XEP]; Ah[ks][3]=aph[8*XEP+4];
            Al[ks][0]=apl[0]; Al[ks][2]=apl[4];
            Al[ks][1]=apl[8*XEP]; Al[ks][3]=apl[8*XEP+4];
        }

        // main task: 32 cols (nj = 0..3)
        float acc[4][4];
        #pragma unroll
        for (int nj = 0; nj < 4; nj++)
            #pragma unroll
            for (int q = 0; q < 4; q++) acc[nj][q] = 0.f;
        #pragma unroll
        for (int ks = 0; ks < 6; ks++) {
            #pragma unroll
            for (int nj = 0; nj < 4; nj++) {
                int row = ng*32 + nj*8 + g4;
                const uint32_t* bh = ws  + row*XEP + ks*8 + t4;
                const uint32_t* bl = qkw + row*XEP + ks*8 + t4;
                uint32_t bh0 = bh[0], bh1 = bh[4];
                uint32_t bl0 = bl[0], bl1 = bl[4];
                mma16(acc[nj], Ah[ks][0],Ah[ks][1],Ah[ks][2],Ah[ks][3], bh0,bh1);
                mma16(acc[nj], Ah[ks][0],Ah[ks][1],Ah[ks][2],Ah[ks][3], bl0,bl1);
                mma16(acc[nj], Al[ks][0],Al[ks][1],Al[ks][2],Al[ks][3], bh0,bh1);
            }
        }
        #pragma unroll
        for (int nj = 0; nj < 4; nj++) {
            int u = ng*32 + nj*8 + 2*t4;
            float bb0 = extra_b[u], bb1 = extra_b[u+1];
            long tok = m0tok + mt*16 + g4;
            *(float2*)&out[tok*512 + 240 + u] =
                make_float2(acc[nj][0]+bb0, acc[nj][1]+bb1);
            *(float2*)&out[(tok+8)*512 + 240 + u] =
                make_float2(acc[nj][2]+bb0, acc[nj][3]+bb1);
        }

        // tail: cols 256-271 handled by warps 0 (mt0) and 8 (mt1)
        if (ng == 0) {
            float acct[2][4];
            #pragma unroll
            for (int nj = 0; nj < 2; nj++)
                #pragma unroll
                for (int q = 0; q < 4; q++) acct[nj][q] = 0.f;
            #pragma unroll
            for (int ks = 0; ks < 6; ks++) {
                #pragma unroll
                for (int nj = 0; nj < 2; nj++) {
                    int row = 256 + nj*8 + g4;
                    const uint32_t* bh = ws  + row*XEP + ks*8 + t4;
                    const uint32_t* bl = qkw + row*XEP + ks*8 + t4;
                    uint32_t bh0 = bh[0], bh1 = bh[4];
                    uint32_t bl0 = bl[0], bl1 = bl[4];
                    mma16(acct[nj], Ah[ks][0],Ah[ks][1],Ah[ks][2],Ah[ks][3], bh0,bh1);
                    mma16(acct[nj], Ah[ks][0],Ah[ks][1],Ah[ks][2],Ah[ks][3], bl0,bl1);
                    mma16(acct[nj], Al[ks][0],Al[ks][1],Al[ks][2],Al[ks][3], bh0,bh1);
                }
            }
            #pragma unroll
            for (int nj = 0; nj < 2; nj++) {
                int u = 256 + nj*8 + 2*t4;
                float bb0 = extra_b[u], bb1 = extra_b[u+1];
                long tok = m0tok + mt*16 + g4;
                *(float2*)&out[tok*512 + 240 + u] =
                    make_float2(acct[nj][0]+bb0, acct[nj][1]+bb1);
                *(float2*)&out[(tok+8)*512 + 240 + u] =
                    make_float2(acct[nj][2]+bb0, acct[nj][3]+bb1);
            }
        }
    }
}

extern "C" void kernel_launch(void* const* d_in, const int* in_sizes, int n_in,
                              void* d_out, int out_size)
{
    const float *x=0, *agg_W=0, *agg_b=0, *ipw=0, *ipb=0, *out_w=0, *out_b=0, *extra_w=0, *extra_b=0;
    for (int i = 0; i < n_in; i++) {
        switch (in_sizes[i]) {
            case 32*4096*256: x       = (const float*)d_in[i]; break;
            case 5*48*32:     agg_W   = (const float*)d_in[i]; break;
            case 5*48:        agg_b   = (const float*)d_in[i]; break;
            case 144*48:      ipw     = (const float*)d_in[i]; break;
            case 144:         ipb     = (const float*)d_in[i]; break;
            case 48*48:       out_w   = (const float*)d_in[i]; break;
            case 48:          out_b   = (const float*)d_in[i]; break;
            case 272*96:      extra_w = (const float*)d_in[i]; break;
            case 272:         extra_b = (const float*)d_in[i]; break;
            default: break;
        }
    }
    float* out = (float*)d_out;

    prep_kernel<<<17, PREP_T>>>(agg_W, agg_b, ipw, ipb, out_w, extra_w);

    const int smem_bytes = SM_WORDS * 4;   // 222400
    cudaFuncSetAttribute(main_kernel, cudaFuncAttributeMaxDynamicSharedMemorySize, smem_bytes);
    main_kernel<<<NBLOCKS, THREADS, smem_bytes>>>(x, extra_b, out_b, out);
}

// round 7
// speedup vs baseline: 2.6403x; 1.2455x over previous
#include <cuda_runtime.h>
#include <cuda_bf16.h>
#include <cstdint>

#define AA 5
#define THREADS 512
#define ROWS_PB 160
#define GROUPS_PB 32
#define NBLOCKS 4096

// ---------------- precomputed fused weights ---------------------------------
__device__ uint32_t g_Wqk_hp[AA][96][16];
__device__ uint32_t g_Wqk_lp[AA][96][16];
__device__ float    g_bqk  [AA][96];
__device__ uint32_t g_Wvo_hp[AA][96][16];
__device__ uint32_t g_Wvo_lp[AA][96][16];
__device__ float    g_bvo  [AA][96];
// extra weights in MMA-fragment layout: [(tile*6+ks)*32 + lane] = (bh0,bh1,bl0,bl1)
__device__ uint4    g_EWf[34*6*32];

__device__ __forceinline__ void split_bf16(float v, float& h, float& l) {
    h = __bfloat162float(__float2bfloat16_rn(v));
    l = v - h;
}

// pack: lo_e -> bits[15:0], hi_e -> bits[31:16]
__device__ __forceinline__ uint32_t packbf(float lo_e, float hi_e) {
    uint32_t r;
    asm("cvt.rn.bf16x2.f32 %0, %1, %2;" : "=r"(r) : "f"(hi_e), "f"(lo_e));
    return r;
}

__device__ __forceinline__ void mma16(float* d,
                                      uint32_t a0, uint32_t a1, uint32_t a2, uint32_t a3,
                                      uint32_t b0, uint32_t b1) {
    asm volatile("mma.sync.aligned.m16n8k16.row.col.f32.bf16.bf16.f32 "
                 "{%0,%1,%2,%3}, {%4,%5,%6,%7}, {%8,%9}, {%0,%1,%2,%3};"
                 : "+f"(d[0]), "+f"(d[1]), "+f"(d[2]), "+f"(d[3])
                 : "r"(a0), "r"(a1), "r"(a2), "r"(a3), "r"(b0), "r"(b1));
}

#define BAR_A() asm volatile("bar.sync 1, 256;" ::: "memory")

// ---------------------------- prep kernel ----------------------------------
#define PREP_T 256
__global__ void prep_kernel(const float* __restrict__ agg_W,
                            const float* __restrict__ agg_b,
                            const float* __restrict__ ipw,
                            const float* __restrict__ ipb,
                            const float* __restrict__ out_w,
                            const float* __restrict__ extra_w)
{
    int bid = blockIdx.x;
    if (bid < AA) {
        int a = bid;
        for (int o = threadIdx.x; o < 96*16; o += PREP_T) {
            int j = o >> 4, w = o & 15;
            float acc0 = 0.f, acc1 = 0.f;
            for (int e = 0; e < 48; e++) {
                float wv = ipw[j*48+e];
                acc0 += wv * agg_W[(a*48+e)*32 + 2*w];
                acc1 += wv * agg_W[(a*48+e)*32 + 2*w+1];
            }
            float h0,l0,h1,l1;
            split_bf16(acc0, h0, l0); split_bf16(acc1, h1, l1);
            g_Wqk_hp[a][j][w] = packbf(h0, h1);
            g_Wqk_lp[a][j][w] = packbf(l0, l1);
        }
        for (int j = threadIdx.x; j < 96; j += PREP_T) {
            float acc = ipb[j];
            for (int e = 0; e < 48; e++)
                acc += ipw[j*48+e] * agg_b[a*48+e];
            g_bqk[a][j] = acc;
        }
    } else if (bid < AA + 2*AA) {
        int a = (bid - AA) >> 1;
        int h = (bid - AA) & 1;
        __shared__ float Wv[24][32];
        __shared__ float bv[24];
        for (int o = threadIdx.x; o < 24*32; o += PREP_T) {
            int d = o >> 5, c = o & 31;
            int row = 96 + h*24 + d;
            float acc = 0.f;
            for (int e = 0; e < 48; e++)
                acc += ipw[row*48+e] * agg_W[(a*48+e)*32 + c];
            Wv[d][c] = acc;
        }
        for (int d = threadIdx.x; d < 24; d += PREP_T) {
            int row = 96 + h*24 + d;
            float acc = ipb[row];
            for (int e = 0; e < 48; e++)
                acc += ipw[row*48+e] * agg_b[a*48+e];
            bv[d] = acc;
        }
        __syncthreads();
        for (int o = threadIdx.x; o < 48*16; o += PREP_T) {
            int e = o >> 4, w = o & 15;
            float acc0 = 0.f, acc1 = 0.f;
            for (int d = 0; d < 24; d++) {
                float ow = out_w[e*48 + h*24 + d];
                acc0 += Wv[d][2*w]   * ow;
                acc1 += Wv[d][2*w+1] * ow;
            }
            float h0,l0,h1,l1;
            split_bf16(acc0, h0, l0); split_bf16(acc1, h1, l1);
            g_Wvo_hp[a][h*48 + e][w] = packbf(h0, h1);
            g_Wvo_lp[a][h*48 + e][w] = packbf(l0, l1);
        }
        for (int e = threadIdx.x; e < 48; e += PREP_T) {
            float acc = 0.f;
            for (int d = 0; d < 24; d++)
                acc += bv[d] * out_w[e*48 + h*24 + d];
            g_bvo[a][h*48 + e] = acc;
        }
    } else {
        // extra_w -> fragment layout; 2 blocks cover 34*6*32 = 6528 uint4
        int part = bid - 3*AA;                // 0 or 1
        int beg = part * 3264;
        int end = beg + 3264;
        for (int o = beg + threadIdx.x; o < end; o += PREP_T) {
            int lane = o & 31;
            int tk   = o >> 5;
            int ks   = tk % 6;
            int t    = tk / 6;
            int g4   = lane >> 2, t4 = lane & 3;
            int row  = t*8 + g4;              // output col (0..271)
            int w0   = ks*8 + t4;
            float v00 = extra_w[row*96 + 2*w0];
            float v01 = extra_w[row*96 + 2*w0 + 1];
            float v10 = extra_w[row*96 + 2*(w0+4)];
            float v11 = extra_w[row*96 + 2*(w0+4) + 1];
            float h00,l00,h01,l01,h10,l10,h11,l11;
            split_bf16(v00,h00,l00); split_bf16(v01,h01,l01);
            split_bf16(v10,h10,l10); split_bf16(v11,h11,l11);
            g_EWf[o] = make_uint4(packbf(h00,h01), packbf(h10,h11),
                                  packbf(l00,l01), packbf(l10,l11));
        }
    }
}

// ---------------------------- main kernel ----------------------------------
// Attention-side shared layout (32-bit words):
//   xsh/xsl : 160 x 20  packed bf16x2 x slices
//   ws      : 2 sets of [hi 96x20][lo 96x20]
//   qkbuf   : fp32, group g at g*528, row j of group at +j*100 (GRP%32==16)
//   pb      : 32 x 50 fp32 softmax probs
#define XSP 20
#define GRP 528
#define SM_XSH 0
#define SM_XSL 3200
#define SM_WS  6400
#define WLO    1920              // 96*20
#define WSET   3840
#define SM_QK  14080
#define SM_PB  30976
#define SM_WORDS 32576           // 130304 bytes

__device__ __forceinline__ long row_xoff(int r)
{
    int a  = (r >> 12) % 5;
    int tx = (r / 20480) * 4096 + (r & 4095);
    return (long)tx * 256 + a * 32;
}

__device__ __forceinline__ void gemm_stage(
    const uint32_t* __restrict__ xsh, const uint32_t* __restrict__ xsl,
    const uint32_t* __restrict__ ws, float* __restrict__ qk,
    const float* __restrict__ bias_lo, const float* __restrict__ bias_hi,
    int warp, int g4, int t4, int r0, int Bnd, bool has_b)
{
    #pragma unroll 1
    for (int tsel = 0; tsel < 3; tsel++) {
        if (tsel == 2 && warp >= 4) break;
        int task = (tsel < 2) ? (warp + tsel*8) : (16 + warp);
        int mt = task >> 1, ng = task & 1;
        bool hiset = has_b && (r0 + mt*16) >= Bnd;
        const uint32_t* wsb = ws + (hiset ? WSET : 0);
        const float* bias = hiset ? bias_hi : bias_lo;
        int arow = mt*16 + g4;

        uint32_t ah[2][4], al[2][4];
        #pragma unroll
        for (int ks = 0; ks < 2; ks++) {
            const uint32_t* aph = xsh + arow*XSP + ks*8 + t4;
            const uint32_t* apl = xsl + arow*XSP + ks*8 + t4;
            ah[ks][0]=aph[0]; ah[ks][2]=aph[4];
            ah[ks][1]=aph[8*XSP]; ah[ks][3]=aph[8*XSP+4];
            al[ks][0]=apl[0]; al[ks][2]=apl[4];
            al[ks][1]=apl[8*XSP]; al[ks][3]=apl[8*XSP+4];
        }

        float acc[6][4];
        #pragma unroll
        for (int nj = 0; nj < 6; nj++)
            #pragma unroll
            for (int q = 0; q < 4; q++) acc[nj][q] = 0.f;

        #pragma unroll
        for (int ks = 0; ks < 2; ks++) {
            #pragma unroll
            for (int nj = 0; nj < 6; nj++) {
                const uint32_t* bp = wsb + (ng*48 + nj*8 + g4)*XSP + ks*8 + t4;
                uint32_t bh0 = bp[0], bh1 = bp[4];
                uint32_t bl0 = bp[WLO], bl1 = bp[WLO+4];
                mma16(acc[nj], ah[ks][0],ah[ks][1],ah[ks][2],ah[ks][3], bh0,bh1);
                mma16(acc[nj], ah[ks][0],ah[ks][1],ah[ks][2],ah[ks][3], bl0,bl1);
                mma16(acc[nj], al[ks][0],al[ks][1],al[ks][2],al[ks][3], bh0,bh1);
            }
        }

        int R0 = mt*16 + g4;
        int R1 = R0 + 8;
        int off0 = (R0/5)*GRP + (R0%5)*100;
        int off1 = (R1/5)*GRP + (R1%5)*100;
        #pragma unroll
        for (int nj = 0; nj < 6; nj++) {
            int col = ng*48 + nj*8 + 2*t4;
            float b0 = bias[col], b1 = bias[col+1];
            *(float2*)&qk[off0 + col] = make_float2(acc[nj][0]+b0, acc[nj][1]+b1);
            *(float2*)&qk[off1 + col] = make_float2(acc[nj][2]+b0, acc[nj][3]+b1);
        }
    }
}

__global__ void __launch_bounds__(THREADS, 1)
main_kernel(const float* __restrict__ x,
            const float* __restrict__ extra_b,
            const float* __restrict__ out_b,
            float* __restrict__ out)
{
    extern __shared__ float sm[];
    uint32_t* smw = (uint32_t*)sm;
    uint32_t* xsh = smw + SM_XSH;
    uint32_t* xsl = smw + SM_XSL;
    uint32_t* ws  = smw + SM_WS;
    float*    qk  = sm  + SM_QK;
    float*    pb  = sm  + SM_PB;

    const int tid  = threadIdx.x;
    const int lane = tid & 31;
    const int warp = tid >> 5;       // 0..15
    const int g4   = lane >> 2;
    const int t4   = lane & 3;

    const int r0    = blockIdx.x * ROWS_PB;
    const int m0tok = blockIdx.x * GROUPS_PB;

    if (warp >= 8) {
        // ==================== EXTRA-FEATURES PIPELINE (warps 8-15) ==========
        // No smem, no barriers. B from fragment-packed global (L2-resident).
        int ew = warp - 8;               // 0..7
        int mt = ew & 1;
        int qw = ew >> 1;                // tile residue class mod 4

        // A fragments: x[tok, 160:256] split to bf16 hi/lo in registers
        uint32_t Ah[6][4], Al[6][4];
        const float* xb = x + (long)(m0tok + mt*16 + g4)*256 + 160;
        #pragma unroll
        for (int ks = 0; ks < 6; ks++) {
            int c0 = (ks*8 + t4)*2;
            float2 v0 = *(const float2*)(xb + c0);
            float2 v2 = *(const float2*)(xb + c0 + 8);
            float2 v1 = *(const float2*)(xb + 2048 + c0);
            float2 v3 = *(const float2*)(xb + 2048 + c0 + 8);
            float h0,l0,h1,l1;
            split_bf16(v0.x,h0,l0); split_bf16(v0.y,h1,l1);
            Ah[ks][0] = packbf(h0,h1); Al[ks][0] = packbf(l0,l1);
            split_bf16(v1.x,h0,l0); split_bf16(v1.y,h1,l1);
            Ah[ks][1] = packbf(h0,h1); Al[ks][1] = packbf(l0,l1);
            split_bf16(v2.x,h0,l0); split_bf16(v2.y,h1,l1);
            Ah[ks][2] = packbf(h0,h1); Al[ks][2] = packbf(l0,l1);
            split_bf16(v3.x,h0,l0); split_bf16(v3.y,h1,l1);
            Ah[ks][3] = packbf(h0,h1); Al[ks][3] = packbf(l0,l1);
        }

        long tokA = m0tok + mt*16 + g4;
        #pragma unroll 1
        for (int t = qw; t < 34; t += 4) {
            float acc[4] = {0.f, 0.f, 0.f, 0.f};
            #pragma unroll
            for (int ks = 0; ks < 6; ks++) {
                uint4 bv = g_EWf[(t*6 + ks)*32 + lane];
                mma16(acc, Ah[ks][0],Ah[ks][1],Ah[ks][2],Ah[ks][3], bv.x, bv.y);
                mma16(acc, Ah[ks][0],Ah[ks][1],Ah[ks][2],Ah[ks][3], bv.z, bv.w);
                mma16(acc, Al[ks][0],Al[ks][1],Al[ks][2],Al[ks][3], bv.x, bv.y);
            }
            int u = t*8 + 2*t4;
            float bb0 = extra_b[u], bb1 = extra_b[u+1];
            *(float2*)&out[tokA*512 + 240 + u] =
                make_float2(acc[0]+bb0, acc[1]+bb1);
            *(float2*)&out[(tokA+8)*512 + 240 + u] =
                make_float2(acc[2]+bb0, acc[3]+bb1);
        }
        return;
    }

    // ==================== ATTENTION PIPELINE (warps 0-7) ====================
    const int z  = tid & 15;
    const int t0 = tid >> 4;             // 0..15

    const int  blk4k = r0 >> 12;
    const int  a_lo  = blk4k % 5;
    const int  Bnd   = (blk4k + 1) << 12;
    const bool has_b = (r0 + ROWS_PB) > Bnd;
    const int  a_hi  = has_b ? ((a_lo + 1) % 5) : a_lo;

    // ---- stage x rows (split + packed) + qk weights ------------------------
    for (int i = tid; i < 1280; i += 256) {        // 160 rows * 8 float4
        int row = i >> 3, q = i & 7;
        const float4 v = *(const float4*)(x + row_xoff(r0 + row) + q*4);
        float h0,l0,h1,l1,h2,l2,h3,l3;
        split_bf16(v.x, h0, l0); split_bf16(v.y, h1, l1);
        split_bf16(v.z, h2, l2); split_bf16(v.w, h3, l3);
        *(uint2*)&xsh[row*XSP + q*2] = make_uint2(packbf(h0,h1), packbf(h2,h3));
        *(uint2*)&xsl[row*XSP + q*2] = make_uint2(packbf(l0,l1), packbf(l2,l3));
    }
    for (int i = tid; i < 96*16; i += 256) {
        int j = i >> 4, w = i & 15;
        ws[j*XSP + w]       = g_Wqk_hp[a_lo][j][w];
        ws[WLO + j*XSP + w] = g_Wqk_lp[a_lo][j][w];
        if (has_b) {
            ws[WSET + j*XSP + w]       = g_Wqk_hp[a_hi][j][w];
            ws[WSET + WLO + j*XSP + w] = g_Wqk_lp[a_hi][j][w];
        }
    }
    BAR_A();

    // ---- qk GEMM -----------------------------------------------------------
    gemm_stage(xsh, xsl, ws, qk, g_bqk[a_lo], g_bqk[a_hi],
               warp, g4, t4, r0, Bnd, has_b);
    BAR_A();

    // ---- softmax + restage ws with vo weights ------------------------------
    if (z < 10) {
        int h = z / 5, ii = z % 5;
        #pragma unroll
        for (int pick = 0; pick < 2; pick++) {
            int g = t0 + pick*16;
            const float* gb = qk + g*GRP;
            float qreg[24];
            const float* qp = gb + ii*100 + h*24;
            #pragma unroll
            for (int d = 0; d < 24; d++) qreg[d] = qp[d];
            float s[5]; float mx = -1e30f;
            #pragma unroll
            for (int j = 0; j < 5; j++) {
                float a = 0.f;
                const float* kp = gb + j*100 + 48 + h*24;
                #pragma unroll
                for (int d = 0; d < 24; d++) a = fmaf(qreg[d], kp[d], a);
                s[j] = a * 0.20412414523193154f;
                mx = fmaxf(mx, s[j]);
            }
            float sum = 0.f;
            #pragma unroll
            for (int j = 0; j < 5; j++) { s[j] = __expf(s[j]-mx); sum += s[j]; }
            float inv = 1.f / sum;
            #pragma unroll
            for (int j = 0; j < 5; j++) pb[g*50 + z*5 + j] = s[j]*inv;
        }
    }
    for (int i = tid; i < 96*16; i += 256) {
        int j = i >> 4, w = i & 15;
        ws[j*XSP + w]       = g_Wvo_hp[a_lo][j][w];
        ws[WLO + j*XSP + w] = g_Wvo_lp[a_lo][j][w];
        if (has_b) {
            ws[WSET + j*XSP + w]       = g_Wvo_hp[a_hi][j][w];
            ws[WSET + WLO + j*XSP + w] = g_Wvo_lp[a_hi][j][w];
        }
    }
    BAR_A();

    // ---- vo GEMM (overwrites qkbuf; softmax already consumed qk) -----------
    gemm_stage(xsh, xsl, ws, qk, g_bvo[a_lo], g_bvo[a_hi],
               warp, g4, t4, r0, Bnd, has_b);
    BAR_A();

    // ---- combine -> out cols [0,240) ----------------------------------------
    #pragma unroll 1
    for (int pick = 0; pick < 2; pick++) {
        int g = t0 + pick*16;
        const float* pg = pb + g*50;
        const float* vg = qk + g*GRP;
        float pc[50];
        #pragma unroll
        for (int k = 0; k < 50; k++) pc[k] = pg[k];
        #pragma unroll
        for (int eidx = 0; eidx < 3; eidx++) {
            int e = z + 16*eidx;
            float vr[10];
            #pragma unroll
            for (int h = 0; h < 2; h++)
                #pragma unroll
                for (int j = 0; j < 5; j++)
                    vr[h*5+j] = vg[j*100 + h*48 + e];
            float ob = out_b[e];
            #pragma unroll
            for (int i = 0; i < 5; i++) {
                float acc = ob;
                #pragma unroll
                for (int h = 0; h < 2; h++)
                    #pragma unroll
                    for (int j = 0; j < 5; j++)
                        acc = fmaf(pc[(h*5+i)*5+j], vr[h*5+j], acc);
                out[(long)(m0tok+g)*512 + i*48 + e] = acc;
            }
        }
    }
}

extern "C" void kernel_launch(void* const* d_in, const int* in_sizes, int n_in,
                              void* d_out, int out_size)
{
    const float *x=0, *agg_W=0, *agg_b=0, *ipw=0, *ipb=0, *out_w=0, *out_b=0, *extra_w=0, *extra_b=0;
    for (int i = 0; i < n_in; i++) {
        switch (in_sizes[i]) {
            case 32*4096*256: x       = (const float*)d_in[i]; break;
            case 5*48*32:     agg_W   = (const float*)d_in[i]; break;
            case 5*48:        agg_b   = (const float*)d_in[i]; break;
            case 144*48:      ipw     = (const float*)d_in[i]; break;
            case 144:         ipb     = (const float*)d_in[i]; break;
            case 48*48:       out_w   = (const float*)d_in[i]; break;
            case 48:          out_b   = (const float*)d_in[i]; break;
            case 272*96:      extra_w = (const float*)d_in[i]; break;
            case 272:         extra_b = (const float*)d_in[i]; break;
            default: break;
        }
    }
    float* out = (float*)d_out;

    prep_kernel<<<17, PREP_T>>>(agg_W, agg_b, ipw, ipb, out_w, extra_w);

    const int smem_bytes = SM_WORDS * 4;   // 130304
    cudaFuncSetAttribute(main_kernel, cudaFuncAttributeMaxDynamicSharedMemorySize, smem_bytes);
    main_kernel<<<NBLOCKS, THREADS, smem_bytes>>>(x, extra_b, out_b, out);
}

// round 8
// speedup vs baseline: 2.7431x; 1.0390x over previous
#include <cuda_runtime.h>
#include <cuda_bf16.h>
#include <cstdint>

#define AA 5
#define THREADS 512
#define ROWS_PB 160
#define GROUPS_PB 32
#define NBLOCKS 4096

// ---------------- precomputed fused weights ---------------------------------
__device__ uint32_t g_Wqk_hp[AA][96][16];
__device__ uint32_t g_Wqk_lp[AA][96][16];
__device__ float    g_bqk  [AA][96];
__device__ uint32_t g_Wvo_hp[AA][96][16];
__device__ uint32_t g_Wvo_lp[AA][96][16];
__device__ float    g_bvo  [AA][96];
// extra weights in MMA-fragment layout: [(tile*6+ks)*32 + lane] = (bh0,bh1,bl0,bl1)
__device__ uint4    g_EWf[34*6*32];

__device__ __forceinline__ void split_bf16(float v, float& h, float& l) {
    h = __bfloat162float(__float2bfloat16_rn(v));
    l = v - h;
}

// pack: lo_e -> bits[15:0], hi_e -> bits[31:16]
__device__ __forceinline__ uint32_t packbf(float lo_e, float hi_e) {
    uint32_t r;
    asm("cvt.rn.bf16x2.f32 %0, %1, %2;" : "=r"(r) : "f"(hi_e), "f"(lo_e));
    return r;
}

__device__ __forceinline__ void mma16(float* d,
                                      uint32_t a0, uint32_t a1, uint32_t a2, uint32_t a3,
                                      uint32_t b0, uint32_t b1) {
    asm volatile("mma.sync.aligned.m16n8k16.row.col.f32.bf16.bf16.f32 "
                 "{%0,%1,%2,%3}, {%4,%5,%6,%7}, {%8,%9}, {%0,%1,%2,%3};"
                 : "+f"(d[0]), "+f"(d[1]), "+f"(d[2]), "+f"(d[3])
                 : "r"(a0), "r"(a1), "r"(a2), "r"(a3), "r"(b0), "r"(b1));
}

#define BAR_A() asm volatile("bar.sync 1, 256;" ::: "memory")

// ---------------------------- prep kernel ----------------------------------
#define PREP_T 256
__global__ void prep_kernel(const float* __restrict__ agg_W,
                            const float* __restrict__ agg_b,
                            const float* __restrict__ ipw,
                            const float* __restrict__ ipb,
                            const float* __restrict__ out_w,
                            const float* __restrict__ extra_w)
{
    int bid = blockIdx.x;
    if (bid < AA) {
        int a = bid;
        for (int o = threadIdx.x; o < 96*16; o += PREP_T) {
            int j = o >> 4, w = o & 15;
            float acc0 = 0.f, acc1 = 0.f;
            for (int e = 0; e < 48; e++) {
                float wv = ipw[j*48+e];
                acc0 += wv * agg_W[(a*48+e)*32 + 2*w];
                acc1 += wv * agg_W[(a*48+e)*32 + 2*w+1];
            }
            float h0,l0,h1,l1;
            split_bf16(acc0, h0, l0); split_bf16(acc1, h1, l1);
            g_Wqk_hp[a][j][w] = packbf(h0, h1);
            g_Wqk_lp[a][j][w] = packbf(l0, l1);
        }
        for (int j = threadIdx.x; j < 96; j += PREP_T) {
            float acc = ipb[j];
            for (int e = 0; e < 48; e++)
                acc += ipw[j*48+e] * agg_b[a*48+e];
            g_bqk[a][j] = acc;
        }
    } else if (bid < AA + 2*AA) {
        int a = (bid - AA) >> 1;
        int h = (bid - AA) & 1;
        __shared__ float Wv[24][32];
        __shared__ float bv[24];
        for (int o = threadIdx.x; o < 24*32; o += PREP_T) {
            int d = o >> 5, c = o & 31;
            int row = 96 + h*24 + d;
            float acc = 0.f;
            for (int e = 0; e < 48; e++)
                acc += ipw[row*48+e] * agg_W[(a*48+e)*32 + c];
            Wv[d][c] = acc;
        }
        for (int d = threadIdx.x; d < 24; d += PREP_T) {
            int row = 96 + h*24 + d;
            float acc = ipb[row];
            for (int e = 0; e < 48; e++)
                acc += ipw[row*48+e] * agg_b[a*48+e];
            bv[d] = acc;
        }
        __syncthreads();
        for (int o = threadIdx.x; o < 48*16; o += PREP_T) {
            int e = o >> 4, w = o & 15;
            float acc0 = 0.f, acc1 = 0.f;
            for (int d = 0; d < 24; d++) {
                float ow = out_w[e*48 + h*24 + d];
                acc0 += Wv[d][2*w]   * ow;
                acc1 += Wv[d][2*w+1] * ow;
            }
            float h0,l0,h1,l1;
            split_bf16(acc0, h0, l0); split_bf16(acc1, h1, l1);
            g_Wvo_hp[a][h*48 + e][w] = packbf(h0, h1);
            g_Wvo_lp[a][h*48 + e][w] = packbf(l0, l1);
        }
        for (int e = threadIdx.x; e < 48; e += PREP_T) {
            float acc = 0.f;
            for (int d = 0; d < 24; d++)
                acc += bv[d] * out_w[e*48 + h*24 + d];
            g_bvo[a][h*48 + e] = acc;
        }
    } else {
        // extra_w -> fragment layout; 2 blocks cover 34*6*32 = 6528 uint4
        int part = bid - 3*AA;                // 0 or 1
        int beg = part * 3264;
        int end = beg + 3264;
        for (int o = beg + threadIdx.x; o < end; o += PREP_T) {
            int lane = o & 31;
            int tk   = o >> 5;
            int ks   = tk % 6;
            int t    = tk / 6;
            int g4   = lane >> 2, t4 = lane & 3;
            int row  = t*8 + g4;              // output col (0..271)
            int w0   = ks*8 + t4;
            float v00 = extra_w[row*96 + 2*w0];
            float v01 = extra_w[row*96 + 2*w0 + 1];
            float v10 = extra_w[row*96 + 2*(w0+4)];
            float v11 = extra_w[row*96 + 2*(w0+4) + 1];
            float h00,l00,h01,l01,h10,l10,h11,l11;
            split_bf16(v00,h00,l00); split_bf16(v01,h01,l01);
            split_bf16(v10,h10,l10); split_bf16(v11,h11,l11);
            g_EWf[o] = make_uint4(packbf(h00,h01), packbf(h10,h11),
                                  packbf(l00,l01), packbf(l10,l11));
        }
    }
}

// ---------------------------- main kernel ----------------------------------
// Attention-side shared layout (32-bit words):
//   xsh/xsl : 160 x 20  packed bf16x2 x slices
//   ws      : 2 sets of [hi 192x20][lo 192x20]  (rows 0-95 qk, 96-191 vo)
//   qk      : fp32 D[160x192]; row r at (r/5)*1008 + (r%5)*200 (16B aligned)
//   pb      : 32 x 52 fp32 softmax probs (16B-aligned rows)
#define XSP 20
#define GRP 1008
#define SM_XSH 0
#define SM_XSL 3200
#define SM_WS  6400
#define WLO    3840              // 192*20
#define WSET   7680
#define SM_QK  21760
#define SM_PB  54016
#define SM_WORDS 55680           // 222720 bytes

__device__ __forceinline__ long row_xoff(int r)
{
    int a  = (r >> 12) % 5;
    int tx = (r / 20480) * 4096 + (r & 4095);
    return (long)tx * 256 + a * 32;
}

__global__ void __launch_bounds__(THREADS, 1)
main_kernel(const float* __restrict__ x,
            const float* __restrict__ extra_b,
            const float* __restrict__ out_b,
            float* __restrict__ out)
{
    extern __shared__ float sm[];
    uint32_t* smw = (uint32_t*)sm;
    uint32_t* xsh = smw + SM_XSH;
    uint32_t* xsl = smw + SM_XSL;
    uint32_t* ws  = smw + SM_WS;
    float*    qk  = sm  + SM_QK;
    float*    pb  = sm  + SM_PB;

    const int tid  = threadIdx.x;
    const int lane = tid & 31;
    const int warp = tid >> 5;       // 0..15
    const int g4   = lane >> 2;
    const int t4   = lane & 3;

    const int r0    = blockIdx.x * ROWS_PB;
    const int m0tok = blockIdx.x * GROUPS_PB;

    if (warp >= 8) {
        // ==================== EXTRA-FEATURES PIPELINE (warps 8-15) ==========
        int ew = warp - 8;               // 0..7
        int mt = ew & 1;
        int qw = ew >> 1;                // tile residue class mod 4

        uint32_t Ah[6][4], Al[6][4];
        const float* xb = x + (long)(m0tok + mt*16 + g4)*256 + 160;
        #pragma unroll
        for (int ks = 0; ks < 6; ks++) {
            int c0 = (ks*8 + t4)*2;
            float2 v0 = *(const float2*)(xb + c0);
            float2 v2 = *(const float2*)(xb + c0 + 8);
            float2 v1 = *(const float2*)(xb + 2048 + c0);
            float2 v3 = *(const float2*)(xb + 2048 + c0 + 8);
            float h0,l0,h1,l1;
            split_bf16(v0.x,h0,l0); split_bf16(v0.y,h1,l1);
            Ah[ks][0] = packbf(h0,h1); Al[ks][0] = packbf(l0,l1);
            split_bf16(v1.x,h0,l0); split_bf16(v1.y,h1,l1);
            Ah[ks][1] = packbf(h0,h1); Al[ks][1] = packbf(l0,l1);
            split_bf16(v2.x,h0,l0); split_bf16(v2.y,h1,l1);
            Ah[ks][2] = packbf(h0,h1); Al[ks][2] = packbf(l0,l1);
            split_bf16(v3.x,h0,l0); split_bf16(v3.y,h1,l1);
            Ah[ks][3] = packbf(h0,h1); Al[ks][3] = packbf(l0,l1);
        }

        long tokA = m0tok + mt*16 + g4;
        #pragma unroll 1
        for (int t = qw; t < 34; t += 4) {
            float acc[4] = {0.f, 0.f, 0.f, 0.f};
            #pragma unroll
            for (int ks = 0; ks < 6; ks++) {
                uint4 bv = g_EWf[(t*6 + ks)*32 + lane];
                mma16(acc, Ah[ks][0],Ah[ks][1],Ah[ks][2],Ah[ks][3], bv.x, bv.y);
                mma16(acc, Ah[ks][0],Ah[ks][1],Ah[ks][2],Ah[ks][3], bv.z, bv.w);
                mma16(acc, Al[ks][0],Al[ks][1],Al[ks][2],Al[ks][3], bv.x, bv.y);
            }
            int u = t*8 + 2*t4;
            float bb0 = extra_b[u], bb1 = extra_b[u+1];
            *(float2*)&out[tokA*512 + 240 + u] =
                make_float2(acc[0]+bb0, acc[1]+bb1);
            *(float2*)&out[(tokA+8)*512 + 240 + u] =
                make_float2(acc[2]+bb0, acc[3]+bb1);
        }
        return;
    }

    // ==================== ATTENTION PIPELINE (warps 0-7) ====================
    const int z  = tid & 15;
    const int t0 = tid >> 4;             // 0..15

    const int  blk4k = r0 >> 12;
    const int  a_lo  = blk4k % 5;
    const int  Bnd   = (blk4k + 1) << 12;
    const bool has_b = (r0 + ROWS_PB) > Bnd;
    const int  a_hi  = has_b ? ((a_lo + 1) % 5) : a_lo;

    // ---- phase 0: stage x rows (split + packed) + BOTH weight blocks -------
    for (int i = tid; i < 1280; i += 256) {        // 160 rows * 8 float4
        int row = i >> 3, q = i & 7;
        const float4 v = *(const float4*)(x + row_xoff(r0 + row) + q*4);
        float h0,l0,h1,l1,h2,l2,h3,l3;
        split_bf16(v.x, h0, l0); split_bf16(v.y, h1, l1);
        split_bf16(v.z, h2, l2); split_bf16(v.w, h3, l3);
        *(uint2*)&xsh[row*XSP + q*2] = make_uint2(packbf(h0,h1), packbf(h2,h3));
        *(uint2*)&xsl[row*XSP + q*2] = make_uint2(packbf(l0,l1), packbf(l2,l3));
    }
    for (int i = tid; i < 192*16; i += 256) {
        int j = i >> 4, w = i & 15;
        uint32_t h0 = (j < 96) ? g_Wqk_hp[a_lo][j][w] : g_Wvo_hp[a_lo][j-96][w];
        uint32_t l0 = (j < 96) ? g_Wqk_lp[a_lo][j][w] : g_Wvo_lp[a_lo][j-96][w];
        ws[j*XSP + w]       = h0;
        ws[WLO + j*XSP + w] = l0;
        if (has_b) {
            uint32_t h1 = (j < 96) ? g_Wqk_hp[a_hi][j][w] : g_Wvo_hp[a_hi][j-96][w];
            uint32_t l1 = (j < 96) ? g_Wqk_lp[a_hi][j][w] : g_Wvo_lp[a_hi][j-96][w];
            ws[WSET + j*XSP + w]       = h1;
            ws[WSET + WLO + j*XSP + w] = l1;
        }
    }
    BAR_A();

    // ---- phase 1: unified GEMM D[160 x 192] (qk cols 0-95, vo 96-191) ------
    #pragma unroll 1
    for (int task = warp; task < 40; task += 8) {
        int mt = task >> 2, ng = task & 3;               // ng: 48-col group
        bool hiset = has_b && (r0 + mt*16) >= Bnd;
        const uint32_t* wsb = ws + (hiset ? WSET : 0);
        int a_t = hiset ? a_hi : a_lo;
        int arow = mt*16 + g4;

        uint32_t ah[2][4], al[2][4];
        #pragma unroll
        for (int ks = 0; ks < 2; ks++) {
            const uint32_t* aph = xsh + arow*XSP + ks*8 + t4;
            const uint32_t* apl = xsl + arow*XSP + ks*8 + t4;
            ah[ks][0]=aph[0]; ah[ks][2]=aph[4];
            ah[ks][1]=aph[8*XSP]; ah[ks][3]=aph[8*XSP+4];
            al[ks][0]=apl[0]; al[ks][2]=apl[4];
            al[ks][1]=apl[8*XSP]; al[ks][3]=apl[8*XSP+4];
        }

        float acc[6][4];
        #pragma unroll
        for (int nj = 0; nj < 6; nj++)
            #pragma unroll
            for (int q = 0; q < 4; q++) acc[nj][q] = 0.f;

        #pragma unroll
        for (int ks = 0; ks < 2; ks++) {
            #pragma unroll
            for (int nj = 0; nj < 6; nj++) {
                const uint32_t* bp = wsb + (ng*48 + nj*8 + g4)*XSP + ks*8 + t4;
                uint32_t bh0 = bp[0], bh1 = bp[4];
                uint32_t bl0 = bp[WLO], bl1 = bp[WLO+4];
                mma16(acc[nj], ah[ks][0],ah[ks][1],ah[ks][2],ah[ks][3], bh0,bh1);
                mma16(acc[nj], ah[ks][0],ah[ks][1],ah[ks][2],ah[ks][3], bl0,bl1);
                mma16(acc[nj], al[ks][0],al[ks][1],al[ks][2],al[ks][3], bh0,bh1);
            }
        }

        int R0 = mt*16 + g4;
        int R1 = R0 + 8;
        int off0 = (R0/5)*GRP + (R0%5)*200;
        int off1 = (R1/5)*GRP + (R1%5)*200;
        const float* bias = (ng < 2) ? g_bqk[a_t] : g_bvo[a_t];
        int cb = (ng & 1) * 48;
        #pragma unroll
        for (int nj = 0; nj < 6; nj++) {
            int jj = nj*8 + 2*t4;
            float b0 = bias[cb + jj], b1 = bias[cb + jj + 1];
            int col = ng*48 + jj;
            *(float2*)&qk[off0 + col] = make_float2(acc[nj][0]+b0, acc[nj][1]+b1);
            *(float2*)&qk[off1 + col] = make_float2(acc[nj][2]+b0, acc[nj][3]+b1);
        }
    }
    BAR_A();

    // ---- phase 2: softmax (vectorized float4 loads) -------------------------
    if (z < 10) {
        int h = z / 5, ii = z % 5;
        #pragma unroll
        for (int pick = 0; pick < 2; pick++) {
            int g = t0 + pick*16;
            const float* gb = qk + g*GRP;
            float4 qv[6];
            const float4* qp = (const float4*)(gb + ii*200 + h*24);
            #pragma unroll
            for (int d = 0; d < 6; d++) qv[d] = qp[d];
            float s[5]; float mx = -1e30f;
            #pragma unroll
            for (int j = 0; j < 5; j++) {
                const float4* kp = (const float4*)(gb + j*200 + 48 + h*24);
                float a = 0.f;
                #pragma unroll
                for (int d = 0; d < 6; d++) {
                    float4 kv = kp[d];
                    a = fmaf(qv[d].x, kv.x, a);
                    a = fmaf(qv[d].y, kv.y, a);
                    a = fmaf(qv[d].z, kv.z, a);
                    a = fmaf(qv[d].w, kv.w, a);
                }
                s[j] = a * 0.20412414523193154f;
                mx = fmaxf(mx, s[j]);
            }
            float sum = 0.f;
            #pragma unroll
            for (int j = 0; j < 5; j++) { s[j] = __expf(s[j]-mx); sum += s[j]; }
            float inv = 1.f / sum;
            #pragma unroll
            for (int j = 0; j < 5; j++) pb[g*52 + z*5 + j] = s[j]*inv;
        }
    }
    __syncwarp();   // pb producer/consumer are the same warp (t0 in {2w,2w+1})

    // ---- phase 3: combine -> out cols [0,240) -------------------------------
    #pragma unroll 1
    for (int pick = 0; pick < 2; pick++) {
        int g = t0 + pick*16;
        const float* pg = pb + g*52;
        const float* vg = qk + g*GRP + 96;
        float pc[50];
        #pragma unroll
        for (int k = 0; k < 12; k++)
            *(float4*)&pc[k*4] = ((const float4*)pg)[k];
        pc[48] = pg[48]; pc[49] = pg[49];
        #pragma unroll
        for (int eidx = 0; eidx < 3; eidx++) {
            int e = z + 16*eidx;
            float vr[10];
            #pragma unroll
            for (int h = 0; h < 2; h++)
                #pragma unroll
                for (int j = 0; j < 5; j++)
                    vr[h*5+j] = vg[j*200 + h*48 + e];
            float ob = out_b[e];
            #pragma unroll
            for (int i = 0; i < 5; i++) {
                float acc = ob;
                #pragma unroll
                for (int h = 0; h < 2; h++)
                    #pragma unroll
                    for (int j = 0; j < 5; j++)
                        acc = fmaf(pc[(h*5+i)*5+j], vr[h*5+j], acc);
                out[(long)(m0tok+g)*512 + i*48 + e] = acc;
            }
        }
    }
}

extern "C" void kernel_launch(void* const* d_in, const int* in_sizes, int n_in,
                              void* d_out, int out_size)
{
    const float *x=0, *agg_W=0, *agg_b=0, *ipw=0, *ipb=0, *out_w=0, *out_b=0, *extra_w=0, *extra_b=0;
    for (int i = 0; i < n_in; i++) {
        switch (in_sizes[i]) {
            case 32*4096*256: x       = (const float*)d_in[i]; break;
            case 5*48*32:     agg_W   = (const float*)d_in[i]; break;
            case 5*48:        agg_b   = (const float*)d_in[i]; break;
            case 144*48:      ipw     = (const float*)d_in[i]; break;
            case 144:         ipb     = (const float*)d_in[i]; break;
            case 48*48:       out_w   = (const float*)d_in[i]; break;
            case 48:          out_b   = (const float*)d_in[i]; break;
            case 272*96:      extra_w = (const float*)d_in[i]; break;
            case 272:         extra_b = (const float*)d_in[i]; break;
            default: break;
        }
    }
    float* out = (float*)d_out;

    prep_kernel<<<17, PREP_T>>>(agg_W, agg_b, ipw, ipb, out_w, extra_w);

    const int smem_bytes = SM_WORDS * 4;   // 222720
    cudaFuncSetAttribute(main_kernel, cudaFuncAttributeMaxDynamicSharedMemorySize, smem_bytes);
    main_kernel<<<NBLOCKS, THREADS, smem_bytes>>>(x, extra_b, out_b, out);
}

// round 9
// speedup vs baseline: 3.5510x; 1.2945x over previous
#include <cuda_runtime.h>
#include <cuda_bf16.h>
#include <cstdint>

#define AA 5
#define THREADS 512
#define ROWS_PB 160
#define GROUPS_PB 32
#define NBLOCKS 4096

// ---------------- precomputed fused weights ---------------------------------
__device__ uint32_t g_Wqk_hp[AA][96][16];
__device__ uint32_t g_Wqk_lp[AA][96][16];
__device__ float    g_bqk  [AA][96];
__device__ uint32_t g_Wvo_hp[AA][96][16];
__device__ uint32_t g_Wvo_lp[AA][96][16];
__device__ float    g_bvo  [AA][96];
// extra weights, MMA-fragment layout: [(tile*6+ks)*32 + lane] = (bh0,bh1,bl0,bl1)
__device__ uint4    g_EWf[34*6*32];
// unified attention weights (qk cols 0-95, vo 96-191), fragment layout per a:
// [a*1536 + ((n*2+ks)*32 + lane)],  n = col-tile 0..23
__device__ uint4    g_WAf[AA*24*2*32];

__device__ __forceinline__ void split_bf16(float v, float& h, float& l) {
    h = __bfloat162float(__float2bfloat16_rn(v));
    l = v - h;
}

// pack: lo_e -> bits[15:0], hi_e -> bits[31:16]
__device__ __forceinline__ uint32_t packbf(float lo_e, float hi_e) {
    uint32_t r;
    asm("cvt.rn.bf16x2.f32 %0, %1, %2;" : "=r"(r) : "f"(hi_e), "f"(lo_e));
    return r;
}

__device__ __forceinline__ void mma16(float* d,
                                      uint32_t a0, uint32_t a1, uint32_t a2, uint32_t a3,
                                      uint32_t b0, uint32_t b1) {
    asm volatile("mma.sync.aligned.m16n8k16.row.col.f32.bf16.bf16.f32 "
                 "{%0,%1,%2,%3}, {%4,%5,%6,%7}, {%8,%9}, {%0,%1,%2,%3};"
                 : "+f"(d[0]), "+f"(d[1]), "+f"(d[2]), "+f"(d[3])
                 : "r"(a0), "r"(a1), "r"(a2), "r"(a3), "r"(b0), "r"(b1));
}

#define BAR_A() asm volatile("bar.sync 1, 256;" ::: "memory")

// ---------------------------- prep kernels ----------------------------------
#define PREP_T 256
__global__ void prep_kernel(const float* __restrict__ agg_W,
                            const float* __restrict__ agg_b,
                            const float* __restrict__ ipw,
                            const float* __restrict__ ipb,
                            const float* __restrict__ out_w,
                            const float* __restrict__ extra_w)
{
    int bid = blockIdx.x;
    if (bid < AA) {
        int a = bid;
        for (int o = threadIdx.x; o < 96*16; o += PREP_T) {
            int j = o >> 4, w = o & 15;
            float acc0 = 0.f, acc1 = 0.f;
            for (int e = 0; e < 48; e++) {
                float wv = ipw[j*48+e];
                acc0 += wv * agg_W[(a*48+e)*32 + 2*w];
                acc1 += wv * agg_W[(a*48+e)*32 + 2*w+1];
            }
            float h0,l0,h1,l1;
            split_bf16(acc0, h0, l0); split_bf16(acc1, h1, l1);
            g_Wqk_hp[a][j][w] = packbf(h0, h1);
            g_Wqk_lp[a][j][w] = packbf(l0, l1);
        }
        for (int j = threadIdx.x; j < 96; j += PREP_T) {
            float acc = ipb[j];
            for (int e = 0; e < 48; e++)
                acc += ipw[j*48+e] * agg_b[a*48+e];
            g_bqk[a][j] = acc;
        }
    } else if (bid < AA + 2*AA) {
        int a = (bid - AA) >> 1;
        int h = (bid - AA) & 1;
        __shared__ float Wv[24][32];
        __shared__ float bv[24];
        for (int o = threadIdx.x; o < 24*32; o += PREP_T) {
            int d = o >> 5, c = o & 31;
            int row = 96 + h*24 + d;
            float acc = 0.f;
            for (int e = 0; e < 48; e++)
                acc += ipw[row*48+e] * agg_W[(a*48+e)*32 + c];
            Wv[d][c] = acc;
        }
        for (int d = threadIdx.x; d < 24; d += PREP_T) {
            int row = 96 + h*24 + d;
            float acc = ipb[row];
            for (int e = 0; e < 48; e++)
                acc += ipw[row*48+e] * agg_b[a*48+e];
            bv[d] = acc;
        }
        __syncthreads();
        for (int o = threadIdx.x; o < 48*16; o += PREP_T) {
            int e = o >> 4, w = o & 15;
            float acc0 = 0.f, acc1 = 0.f;
            for (int d = 0; d < 24; d++) {
                float ow = out_w[e*48 + h*24 + d];
                acc0 += Wv[d][2*w]   * ow;
                acc1 += Wv[d][2*w+1] * ow;
            }
            float h0,l0,h1,l1;
            split_bf16(acc0, h0, l0); split_bf16(acc1, h1, l1);
            g_Wvo_hp[a][h*48 + e][w] = packbf(h0, h1);
            g_Wvo_lp[a][h*48 + e][w] = packbf(l0, l1);
        }
        for (int e = threadIdx.x; e < 48; e += PREP_T) {
            float acc = 0.f;
            for (int d = 0; d < 24; d++)
                acc += bv[d] * out_w[e*48 + h*24 + d];
            g_bvo[a][h*48 + e] = acc;
        }
    } else {
        // extra_w -> fragment layout; 2 blocks cover 34*6*32 = 6528 uint4
        int part = bid - 3*AA;                // 0 or 1
        int beg = part * 3264;
        int end = beg + 3264;
        for (int o = beg + threadIdx.x; o < end; o += PREP_T) {
            int lane = o & 31;
            int tk   = o >> 5;
            int ks   = tk % 6;
            int t    = tk / 6;
            int g4   = lane >> 2, t4 = lane & 3;
            int row  = t*8 + g4;              // output col (0..271)
            int w0   = ks*8 + t4;
            float v00 = extra_w[row*96 + 2*w0];
            float v01 = extra_w[row*96 + 2*w0 + 1];
            float v10 = extra_w[row*96 + 2*(w0+4)];
            float v11 = extra_w[row*96 + 2*(w0+4) + 1];
            float h00,l00,h01,l01,h10,l10,h11,l11;
            split_bf16(v00,h00,l00); split_bf16(v01,h01,l01);
            split_bf16(v10,h10,l10); split_bf16(v11,h11,l11);
            g_EWf[o] = make_uint4(packbf(h00,h01), packbf(h10,h11),
                                  packbf(l00,l01), packbf(l10,l11));
        }
    }
}

// pack unified attention weights (reads g_Wqk_*, g_Wvo_*) into g_WAf
__global__ void prep2_kernel()
{
    int a = blockIdx.x;
    for (int idx = threadIdx.x; idx < 1536; idx += PREP_T) {
        int lane = idx & 31;
        int ks   = (idx >> 5) & 1;
        int n    = idx >> 6;                   // col-tile 0..23
        int j    = n*8 + (lane >> 2);          // output col 0..191
        int w0   = ks*8 + (lane & 3);
        uint32_t bh0, bh1, bl0, bl1;
        if (j < 96) {
            bh0 = g_Wqk_hp[a][j][w0];   bh1 = g_Wqk_hp[a][j][w0+4];
            bl0 = g_Wqk_lp[a][j][w0];   bl1 = g_Wqk_lp[a][j][w0+4];
        } else {
            bh0 = g_Wvo_hp[a][j-96][w0]; bh1 = g_Wvo_hp[a][j-96][w0+4];
            bl0 = g_Wvo_lp[a][j-96][w0]; bl1 = g_Wvo_lp[a][j-96][w0+4];
        }
        g_WAf[a*1536 + idx] = make_uint4(bh0, bh1, bl0, bl1);
    }
}

// ---------------------------- main kernel ----------------------------------
// Attention-side shared layout (32-bit words):
//   qk : fp32 D[160x192]; row r at (r/5)*1008 + (r%5)*200 (16B aligned)
//   pb : 32 x 52 fp32 softmax probs
#define GRP 1008
#define SM_QK  0
#define SM_PB  32256
#define SM_WORDS 33920           // 135680 bytes

__device__ __forceinline__ long row_xoff(int r)
{
    int a  = (r >> 12) % 5;
    int tx = (r / 20480) * 4096 + (r & 4095);
    return (long)tx * 256 + a * 32;
}

__global__ void __launch_bounds__(THREADS, 1)
main_kernel(const float* __restrict__ x,
            const float* __restrict__ extra_b,
            const float* __restrict__ out_b,
            float* __restrict__ out)
{
    extern __shared__ float sm[];
    float* qk = sm + SM_QK;
    float* pb = sm + SM_PB;

    const int tid  = threadIdx.x;
    const int lane = tid & 31;
    const int warp = tid >> 5;       // 0..15
    const int g4   = lane >> 2;
    const int t4   = lane & 3;

    const int r0    = blockIdx.x * ROWS_PB;
    const int m0tok = blockIdx.x * GROUPS_PB;

    if (warp >= 8) {
        // ==================== EXTRA-FEATURES PIPELINE (warps 8-15) ==========
        int ew = warp - 8;               // 0..7
        int mt = ew & 1;
        int qw = ew >> 1;                // tile residue class mod 4

        uint32_t Ah[6][4], Al[6][4];
        const float* xb = x + (long)(m0tok + mt*16 + g4)*256 + 160;
        #pragma unroll
        for (int ks = 0; ks < 6; ks++) {
            int c0 = (ks*8 + t4)*2;
            float2 v0 = *(const float2*)(xb + c0);
            float2 v2 = *(const float2*)(xb + c0 + 8);
            float2 v1 = *(const float2*)(xb + 2048 + c0);
            float2 v3 = *(const float2*)(xb + 2048 + c0 + 8);
            float h0,l0,h1,l1;
            split_bf16(v0.x,h0,l0); split_bf16(v0.y,h1,l1);
            Ah[ks][0] = packbf(h0,h1); Al[ks][0] = packbf(l0,l1);
            split_bf16(v1.x,h0,l0); split_bf16(v1.y,h1,l1);
            Ah[ks][1] = packbf(h0,h1); Al[ks][1] = packbf(l0,l1);
            split_bf16(v2.x,h0,l0); split_bf16(v2.y,h1,l1);
            Ah[ks][2] = packbf(h0,h1); Al[ks][2] = packbf(l0,l1);
            split_bf16(v3.x,h0,l0); split_bf16(v3.y,h1,l1);
            Ah[ks][3] = packbf(h0,h1); Al[ks][3] = packbf(l0,l1);
        }

        long tokA = m0tok + mt*16 + g4;
        #pragma unroll 1
        for (int t = qw; t < 34; t += 4) {
            float acc[4] = {0.f, 0.f, 0.f, 0.f};
            #pragma unroll
            for (int ks = 0; ks < 6; ks++) {
                uint4 bv = g_EWf[(t*6 + ks)*32 + lane];
                mma16(acc, Ah[ks][0],Ah[ks][1],Ah[ks][2],Ah[ks][3], bv.x, bv.y);
                mma16(acc, Ah[ks][0],Ah[ks][1],Ah[ks][2],Ah[ks][3], bv.z, bv.w);
                mma16(acc, Al[ks][0],Al[ks][1],Al[ks][2],Al[ks][3], bv.x, bv.y);
            }
            int u = t*8 + 2*t4;
            float bb0 = extra_b[u], bb1 = extra_b[u+1];
            *(float2*)&out[tokA*512 + 240 + u] =
                make_float2(acc[0]+bb0, acc[1]+bb1);
            *(float2*)&out[(tokA+8)*512 + 240 + u] =
                make_float2(acc[2]+bb0, acc[3]+bb1);
        }
        return;
    }

    // ==================== ATTENTION PIPELINE (warps 0-7) ====================
    const int z  = tid & 15;
    const int t0 = tid >> 4;             // 0..15

    const int  blk4k = r0 >> 12;
    const int  a_lo  = blk4k % 5;
    const int  Bnd   = (blk4k + 1) << 12;
    const bool has_b = (r0 + ROWS_PB) > Bnd;
    const int  a_hi  = has_b ? ((a_lo + 1) % 5) : a_lo;

    // ---- phase 1: GEMM D[160 x 192], A from global (regs), B from g_WAf ----
    {
        int prev_mt = -1;
        uint32_t ah[2][4], al[2][4];
        #pragma unroll 1
        for (int t = 0; t < 5; t++) {
            int task = warp*5 + t;                       // 4 of 5 share mt
            int mt = task >> 2, ng = task & 3;
            bool hiset = has_b && (r0 + mt*16) >= Bnd;
            int a_t = hiset ? a_hi : a_lo;

            if (mt != prev_mt) {
                prev_mt = mt;
                const float* xA = x + row_xoff(r0 + mt*16 + g4);
                const float* xB = x + row_xoff(r0 + mt*16 + g4 + 8);
                #pragma unroll
                for (int ks = 0; ks < 2; ks++) {
                    int c0 = (ks*8 + t4)*2;
                    float2 vA0 = *(const float2*)(xA + c0);
                    float2 vA2 = *(const float2*)(xA + c0 + 8);
                    float2 vB0 = *(const float2*)(xB + c0);
                    float2 vB2 = *(const float2*)(xB + c0 + 8);
                    float h0,l0,h1,l1;
                    split_bf16(vA0.x,h0,l0); split_bf16(vA0.y,h1,l1);
                    ah[ks][0] = packbf(h0,h1); al[ks][0] = packbf(l0,l1);
                    split_bf16(vB0.x,h0,l0); split_bf16(vB0.y,h1,l1);
                    ah[ks][1] = packbf(h0,h1); al[ks][1] = packbf(l0,l1);
                    split_bf16(vA2.x,h0,l0); split_bf16(vA2.y,h1,l1);
                    ah[ks][2] = packbf(h0,h1); al[ks][2] = packbf(l0,l1);
                    split_bf16(vB2.x,h0,l0); split_bf16(vB2.y,h1,l1);
                    ah[ks][3] = packbf(h0,h1); al[ks][3] = packbf(l0,l1);
                }
            }

            const uint4* wf = g_WAf + a_t*1536;
            float acc[6][4];
            #pragma unroll
            for (int nj = 0; nj < 6; nj++)
                #pragma unroll
                for (int q = 0; q < 4; q++) acc[nj][q] = 0.f;

            #pragma unroll
            for (int ks = 0; ks < 2; ks++) {
                #pragma unroll
                for (int nj = 0; nj < 6; nj++) {
                    uint4 bv = wf[((ng*6 + nj)*2 + ks)*32 + lane];
                    mma16(acc[nj], ah[ks][0],ah[ks][1],ah[ks][2],ah[ks][3], bv.x, bv.y);
                    mma16(acc[nj], ah[ks][0],ah[ks][1],ah[ks][2],ah[ks][3], bv.z, bv.w);
                    mma16(acc[nj], al[ks][0],al[ks][1],al[ks][2],al[ks][3], bv.x, bv.y);
                }
            }

            int R0 = mt*16 + g4;
            int R1 = R0 + 8;
            int off0 = (R0/5)*GRP + (R0%5)*200;
            int off1 = (R1/5)*GRP + (R1%5)*200;
            const float* bias = (ng < 2) ? g_bqk[a_t] : g_bvo[a_t];
            int cb = (ng & 1) * 48;
            #pragma unroll
            for (int nj = 0; nj < 6; nj++) {
                int jj = nj*8 + 2*t4;
                float b0 = bias[cb + jj], b1 = bias[cb + jj + 1];
                int col = ng*48 + jj;
                *(float2*)&qk[off0 + col] = make_float2(acc[nj][0]+b0, acc[nj][1]+b1);
                *(float2*)&qk[off1 + col] = make_float2(acc[nj][2]+b0, acc[nj][3]+b1);
            }
        }
    }
    BAR_A();

    // ---- phase 2: softmax (vectorized float4 loads) -------------------------
    if (z < 10) {
        int h = z / 5, ii = z % 5;
        #pragma unroll
        for (int pick = 0; pick < 2; pick++) {
            int g = t0 + pick*16;
            const float* gb = qk + g*GRP;
            float4 qv[6];
            const float4* qp = (const float4*)(gb + ii*200 + h*24);
            #pragma unroll
            for (int d = 0; d < 6; d++) qv[d] = qp[d];
            float s[5]; float mx = -1e30f;
            #pragma unroll
            for (int j = 0; j < 5; j++) {
                const float4* kp = (const float4*)(gb + j*200 + 48 + h*24);
                float a = 0.f;
                #pragma unroll
                for (int d = 0; d < 6; d++) {
                    float4 kv = kp[d];
                    a = fmaf(qv[d].x, kv.x, a);
                    a = fmaf(qv[d].y, kv.y, a);
                    a = fmaf(qv[d].z, kv.z, a);
                    a = fmaf(qv[d].w, kv.w, a);
                }
                s[j] = a * 0.20412414523193154f;
                mx = fmaxf(mx, s[j]);
            }
            float sum = 0.f;
            #pragma unroll
            for (int j = 0; j < 5; j++) { s[j] = __expf(s[j]-mx); sum += s[j]; }
            float inv = 1.f / sum;
            #pragma unroll
            for (int j = 0; j < 5; j++) pb[g*52 + z*5 + j] = s[j]*inv;
        }
    }
    __syncwarp();   // pb producer/consumer are the same warp (t0 in {2w,2w+1})

    // ---- phase 3: combine -> out cols [0,240) -------------------------------
    #pragma unroll 1
    for (int pick = 0; pick < 2; pick++) {
        int g = t0 + pick*16;
        const float* pg = pb + g*52;
        const float* vg = qk + g*GRP + 96;
        float pc[50];
        #pragma unroll
        for (int k = 0; k < 12; k++)
            *(float4*)&pc[k*4] = ((const float4*)pg)[k];
        pc[48] = pg[48]; pc[49] = pg[49];
        #pragma unroll
        for (int eidx = 0; eidx < 3; eidx++) {
            int e = z + 16*eidx;
            float vr[10];
            #pragma unroll
            for (int h = 0; h < 2; h++)
                #pragma unroll
                for (int j = 0; j < 5; j++)
                    vr[h*5+j] = vg[j*200 + h*48 + e];
            float ob = out_b[e];
            #pragma unroll
            for (int i = 0; i < 5; i++) {
                float acc = ob;
                #pragma unroll
                for (int h = 0; h < 2; h++)
                    #pragma unroll
                    for (int j = 0; j < 5; j++)
                        acc = fmaf(pc[(h*5+i)*5+j], vr[h*5+j], acc);
                out[(long)(m0tok+g)*512 + i*48 + e] = acc;
            }
        }
    }
}

extern "C" void kernel_launch(void* const* d_in, const int* in_sizes, int n_in,
                              void* d_out, int out_size)
{
    const float *x=0, *agg_W=0, *agg_b=0, *ipw=0, *ipb=0, *out_w=0, *out_b=0, *extra_w=0, *extra_b=0;
    for (int i = 0; i < n_in; i++) {
        switch (in_sizes[i]) {
            case 32*4096*256: x       = (const float*)d_in[i]; break;
            case 5*48*32:     agg_W   = (const float*)d_in[i]; break;
            case 5*48:        agg_b   = (const float*)d_in[i]; break;
            case 144*48:      ipw     = (const float*)d_in[i]; break;
            case 144:         ipb     = (const float*)d_in[i]; break;
            case 48*48:       out_w   = (const float*)d_in[i]; break;
            case 48:          out_b   = (const float*)d_in[i]; break;
            case 272*96:      extra_w = (const float*)d_in[i]; break;
            case 272:         extra_b = (const float*)d_in[i]; break;
            default: break;
        }
    }
    float* out = (float*)d_out;

    prep_kernel<<<17, PREP_T>>>(agg_W, agg_b, ipw, ipb, out_w, extra_w);
    prep2_kernel<<<AA, PREP_T>>>();

    const int smem_bytes = SM_WORDS * 4;   // 135680
    cudaFuncSetAttribute(main_kernel, cudaFuncAttributeMaxDynamicSharedMemorySize, smem_bytes);
    main_kernel<<<NBLOCKS, THREADS, smem_bytes>>>(x, extra_b, out_b, out);
}